// round 8
// baseline (speedup 1.0000x reference)
#include <cuda_runtime.h>
#include <cuda_bf16.h>
#include <math.h>
#include <stdint.h>

// ---------------- problem constants ----------------
#define B_ 4
#define T_ 1024
#define D_ 1024
#define H_ 16
#define S_ 64
#define HID_ 3072
#define NTOK (B_*T_)            // 4096

// ---------------- device scratch ----------------
__device__ float g_fwq[D_*D_];
__device__ float g_fwk[D_*D_];
__device__ float g_h[(size_t)NTOK*HID_];            // QKV output, then MLP hidden (fp32)
__device__ unsigned g_maxabs[8];

// bf16 3-term split buffers
__device__ __nv_bfloat16 e_x  [(size_t)NTOK*3*D_];        // activations A-side
__device__ __nv_bfloat16 e_h  [(size_t)NTOK*3*HID_];      // mlp hidden A-side
__device__ __nv_bfloat16 e_qkv[(size_t)(3*D_)*3*D_];      // fused QKV weights B-side
__device__ __nv_bfloat16 e_wo [(size_t)D_*3*D_];
__device__ __nv_bfloat16 e_up [(size_t)HID_*3*D_];
__device__ __nv_bfloat16 e_dn [(size_t)D_*3*HID_];

// ---------------- PTX helpers ----------------
__device__ __forceinline__ uint32_t s2u(const void* p) {
    uint32_t a;
    asm("{ .reg .u64 t; cvta.to.shared.u64 t, %1; cvt.u32.u64 %0, t; }" : "=r"(a) : "l"(p));
    return a;
}
__device__ __forceinline__ void ldsm4(uint32_t* r, uint32_t a) {
    asm volatile("ldmatrix.sync.aligned.m8n8.x4.shared.b16 {%0,%1,%2,%3}, [%4];"
        : "=r"(r[0]), "=r"(r[1]), "=r"(r[2]), "=r"(r[3]) : "r"(a));
}
__device__ __forceinline__ void ldsm4t(uint32_t* r, uint32_t a) {
    asm volatile("ldmatrix.sync.aligned.m8n8.x4.trans.shared.b16 {%0,%1,%2,%3}, [%4];"
        : "=r"(r[0]), "=r"(r[1]), "=r"(r[2]), "=r"(r[3]) : "r"(a));
}
__device__ __forceinline__ void mma16816(float* c, const uint32_t* a, const uint32_t* b) {
    asm volatile("mma.sync.aligned.m16n8k16.row.col.f32.bf16.bf16.f32 "
        "{%0,%1,%2,%3}, {%4,%5,%6,%7}, {%8,%9}, {%0,%1,%2,%3};"
        : "+f"(c[0]), "+f"(c[1]), "+f"(c[2]), "+f"(c[3])
        : "r"(a[0]), "r"(a[1]), "r"(a[2]), "r"(a[3]), "r"(b[0]), "r"(b[1]));
}
__device__ __forceinline__ void cpasync16(uint32_t dst, const void* src) {
    asm volatile("cp.async.cg.shared.global [%0], [%1], 16;" :: "r"(dst), "l"(src));
}
__device__ __forceinline__ uint32_t packbf(float lo, float hi) {
    uint32_t r;
    asm("cvt.rn.bf16x2.f32 %0, %1, %2;" : "=r"(r) : "f"(hi), "f"(lo));
    return r;
}

// ---------------- bf16 HMMA GEMM: C[M,N] = A[M,K3] @ B[N,K3]^T (+Res) ----------------
// CTA tile 128x256, 8 warps (2x4), warp tile 64x64, K-chunk 64, double-buffered cp.async.
#define MMX_SMEM 98304
__global__ __launch_bounds__(256, 1) void mm_hmma(const __nv_bfloat16* __restrict__ Ag,
                                                  const __nv_bfloat16* __restrict__ Bg,
                                                  const float* __restrict__ Res,
                                                  float* __restrict__ C,
                                                  int M, int N, int K3) {
    extern __shared__ char sm_[];
    uint32_t sbase = s2u(sm_);
    int tid = threadIdx.x, lane = tid & 31, wid = tid >> 5;
    int wm = wid >> 2, wn = wid & 3;
    int m0 = blockIdx.y * 128, n0 = blockIdx.x * 256;
    const __nv_bfloat16* Ap = Ag + (size_t)m0 * K3;
    const __nv_bfloat16* Bp = Bg + (size_t)n0 * K3;
    int NC = K3 >> 6;

    float c[4][8][4];
    #pragma unroll
    for (int i = 0; i < 4; ++i)
        #pragma unroll
        for (int j = 0; j < 8; ++j)
            #pragma unroll
            for (int e = 0; e < 4; ++e) c[i][j][e] = 0.f;

    int crow = tid >> 3, cch = tid & 7;

    #define COPY_CHUNK(cidx, buf) do {                                             \
        uint32_t Ab_ = sbase + (buf) * 49152;                                      \
        uint32_t Bb_ = Ab_ + 16384;                                                \
        int kc_ = (cidx) << 6;                                                     \
        _Pragma("unroll")                                                          \
        for (int i_ = 0; i_ < 4; ++i_) {                                           \
            int row_ = crow + i_ * 32;                                             \
            uint32_t dst_ = Ab_ + row_ * 128 + (((cch) ^ (row_ & 7)) << 4);        \
            cpasync16(dst_, Ap + (size_t)row_ * K3 + kc_ + cch * 8);               \
        }                                                                          \
        _Pragma("unroll")                                                          \
        for (int i_ = 0; i_ < 8; ++i_) {                                           \
            int row_ = crow + i_ * 32;                                             \
            uint32_t dst_ = Bb_ + row_ * 128 + (((cch) ^ (row_ & 7)) << 4);        \
            cpasync16(dst_, Bp + (size_t)row_ * K3 + kc_ + cch * 8);               \
        }                                                                          \
        asm volatile("cp.async.commit_group;" ::: "memory");                       \
    } while (0)

    COPY_CHUNK(0, 0);
    for (int c0 = 0; c0 < NC; ++c0) {
        int buf = c0 & 1;
        if (c0 + 1 < NC) {
            COPY_CHUNK(c0 + 1, buf ^ 1);
            asm volatile("cp.async.wait_group 1;" ::: "memory");
        } else {
            asm volatile("cp.async.wait_group 0;" ::: "memory");
        }
        __syncthreads();
        uint32_t Ab = sbase + buf * 49152;
        uint32_t Bb = Ab + 16384;
        #pragma unroll
        for (int ks = 0; ks < 4; ++ks) {
            uint32_t a[4][4], b[4][4];
            // A: fragment order (m0-7,k0-7),(m8-15,k0-7),(m0-7,k8-15),(m8-15,k8-15)
            {
                int ch = ks * 2 + (lane >> 4);
                #pragma unroll
                for (int i = 0; i < 4; ++i) {
                    int row = wm * 64 + i * 16 + (lane & 15);
                    ldsm4(a[i], Ab + row * 128 + ((ch ^ (row & 7)) << 4));
                }
            }
            // B: lane groups deliver {n0-7 frag}, then {n8-15 frag}:
            //   lanes 0-7: rows n0-7 k-lo | lanes 8-15: rows n0-7 k-hi
            //   lanes 16-23: rows n8-15 k-lo | lanes 24-31: rows n8-15 k-hi
            {
                int ch = ks * 2 + ((lane >> 3) & 1);
                #pragma unroll
                for (int j = 0; j < 4; ++j) {
                    int row = wn * 64 + j * 16 + ((lane >> 4) & 1) * 8 + (lane & 7);
                    ldsm4(b[j], Bb + row * 128 + ((ch ^ (row & 7)) << 4));
                }
            }
            #pragma unroll
            for (int i = 0; i < 4; ++i)
                #pragma unroll
                for (int jj = 0; jj < 8; ++jj)
                    mma16816(c[i][jj], a[i], &b[jj >> 1][(jj & 1) * 2]);
        }
        __syncthreads();
    }
    #undef COPY_CHUNK

    int g = lane >> 2, tg = lane & 3;
    #pragma unroll
    for (int i = 0; i < 4; ++i) {
        int r0 = m0 + wm * 64 + i * 16 + g;
        #pragma unroll
        for (int jj = 0; jj < 8; ++jj) {
            int cc = n0 + wn * 64 + jj * 8 + tg * 2;
            float* p0 = C + (size_t)r0 * N + cc;
            float* p1 = C + (size_t)(r0 + 8) * N + cc;
            if (Res) {
                float2 v0 = *(const float2*)(Res + (size_t)r0 * N + cc);
                float2 v1 = *(const float2*)(Res + (size_t)(r0 + 8) * N + cc);
                *(float2*)p0 = make_float2(c[i][jj][0] + v0.x, c[i][jj][1] + v0.y);
                *(float2*)p1 = make_float2(c[i][jj][2] + v1.x, c[i][jj][3] + v1.y);
            } else {
                *(float2*)p0 = make_float2(c[i][jj][0], c[i][jj][1]);
                *(float2*)p1 = make_float2(c[i][jj][2], c[i][jj][3]);
            }
        }
    }
}

// ---------------- fused flash attention (unchanged from R4) ----------------
#define FL_SMEM 95232
__global__ __launch_bounds__(256, 2) void flash_k(const float* __restrict__ qkv,
                                                  const float* __restrict__ p_scale,
                                                  __nv_bfloat16* __restrict__ exo) {
    extern __shared__ char sm_[];
    uint32_t sb = s2u(sm_);
    const uint32_t sQ = sb, sK = sb + 51200, sVh = sb + 76800, sVl = sb + 86016;
    __nv_bfloat16* Qs = (__nv_bfloat16*)sm_;
    __nv_bfloat16* Ks = (__nv_bfloat16*)(sm_ + 51200);
    __nv_bfloat16* Vh = (__nv_bfloat16*)(sm_ + 76800);
    __nv_bfloat16* Vl = (__nv_bfloat16*)(sm_ + 86016);

    int tid = threadIdx.x, lane = tid & 31, wid = tid >> 5;
    int qt = 7 - (int)blockIdx.x;
    int bh = blockIdx.y, b = bh >> 4, h = bh & 15;

    const float* Qg = qkv + ((size_t)(b * T_ + qt * 128)) * 3072 + h * 64;
    const float* Kg = qkv + (size_t)(b * T_) * 3072 + 1024 + h * 64;
    const float* Vg = qkv + (size_t)(b * T_) * 3072 + 2048 + h * 64;

    #pragma unroll
    for (int i = 0; i < 8; ++i) {
        int idx = tid + i * 256;
        int r = idx >> 4, c4 = (idx & 15) * 4;
        float4 v = *(const float4*)(Qg + (size_t)r * 3072 + c4);
        float vv[4] = {v.x, v.y, v.z, v.w};
        #pragma unroll
        for (int j = 0; j < 4; ++j) {
            __nv_bfloat16 hi = __float2bfloat16(vv[j]);
            __nv_bfloat16 lo = __float2bfloat16(vv[j] - __bfloat162float(hi));
            Qs[r * 200 + c4 + j] = hi;
            Qs[r * 200 + 64 + c4 + j] = lo;
            Qs[r * 200 + 128 + c4 + j] = hi;
        }
    }

    float m0 = -INFINITY, m1 = -INFINITY, l0 = 0.f, l1 = 0.f;
    float O[8][4];
    #pragma unroll
    for (int j = 0; j < 8; ++j)
        #pragma unroll
        for (int e = 0; e < 4; ++e) O[j][e] = 0.f;

    float ps = p_scale[0];
    int g = lane >> 2, tg = lane & 3;
    int wr0 = wid * 16;
    int row_g0 = qt * 128 + wr0 + g;
    int nch = (qt * 128 + 128) >> 6;

    uint32_t aq_base = sQ + (wr0 + (lane & 15)) * 400 + (lane >> 4) * 16;
    uint32_t bk_base = sK + (((lane >> 3) & 2) * 4 + (lane & 7)) * 400 + ((lane >> 3) & 1) * 16;
    uint32_t v_roff = ((lane & 7) + ((lane >> 3) & 1) * 8) * 144 + ((lane >> 4) & 1) * 16;

    for (int ch = 0; ch < nch; ++ch) {
        int u0 = ch << 6;
        __syncthreads();
        #pragma unroll
        for (int i = 0; i < 4; ++i) {
            int idx = tid + i * 256;
            int r = idx >> 4, c4 = (idx & 15) * 4;
            float4 kv = *(const float4*)(Kg + (size_t)(u0 + r) * 3072 + c4);
            float4 vv = *(const float4*)(Vg + (size_t)(u0 + r) * 3072 + c4);
            float ka[4] = {kv.x, kv.y, kv.z, kv.w};
            float va[4] = {vv.x, vv.y, vv.z, vv.w};
            #pragma unroll
            for (int j = 0; j < 4; ++j) {
                __nv_bfloat16 khi = __float2bfloat16(ka[j]);
                __nv_bfloat16 klo = __float2bfloat16(ka[j] - __bfloat162float(khi));
                Ks[r * 200 + c4 + j] = khi;
                Ks[r * 200 + 64 + c4 + j] = khi;
                Ks[r * 200 + 128 + c4 + j] = klo;
                __nv_bfloat16 vhi = __float2bfloat16(va[j]);
                __nv_bfloat16 vlo = __float2bfloat16(va[j] - __bfloat162float(vhi));
                Vh[r * 72 + c4 + j] = vhi;
                Vl[r * 72 + c4 + j] = vlo;
            }
        }
        __syncthreads();

        float c[8][4];
        #pragma unroll
        for (int j = 0; j < 8; ++j)
            #pragma unroll
            for (int e = 0; e < 4; ++e) c[j][e] = 0.f;
        #pragma unroll
        for (int ks = 0; ks < 12; ++ks) {
            uint32_t a[4];
            ldsm4(a, aq_base + ks * 32);
            #pragma unroll
            for (int jp = 0; jp < 4; ++jp) {
                uint32_t bb[4];
                ldsm4(bb, bk_base + jp * 16 * 400 + ks * 32);
                mma16816(c[jp * 2], a, bb);
                mma16816(c[jp * 2 + 1], a, bb + 2);
            }
        }

        #pragma unroll
        for (int j = 0; j < 8; ++j) {
            int ub = u0 + j * 8 + tg * 2;
            #pragma unroll
            for (int e = 0; e < 4; ++e) {
                int row = row_g0 + (e >> 1) * 8;
                int u = ub + (e & 1);
                int d = row - u;
                if (d < 0) c[j][e] = -INFINITY;
                else {
                    float bias;
                    if (d == 0) bias = 1.f;
                    else {
                        int vp = __ffs(d) - 1;
                        vp = vp > 16 ? 16 : vp;
                        bias = (float)vp * (1.f / 16.f);
                    }
                    c[j][e] = c[j][e] * 0.125f + ps * bias;
                }
            }
        }

        float mx0 = -INFINITY, mx1 = -INFINITY;
        #pragma unroll
        for (int j = 0; j < 8; ++j) {
            mx0 = fmaxf(mx0, fmaxf(c[j][0], c[j][1]));
            mx1 = fmaxf(mx1, fmaxf(c[j][2], c[j][3]));
        }
        mx0 = fmaxf(mx0, __shfl_xor_sync(0xffffffffu, mx0, 1));
        mx0 = fmaxf(mx0, __shfl_xor_sync(0xffffffffu, mx0, 2));
        mx1 = fmaxf(mx1, __shfl_xor_sync(0xffffffffu, mx1, 1));
        mx1 = fmaxf(mx1, __shfl_xor_sync(0xffffffffu, mx1, 2));
        float mn0 = fmaxf(m0, mx0), mn1 = fmaxf(m1, mx1);
        float al0 = __expf(m0 - mn0), al1 = __expf(m1 - mn1);
        float s0 = 0.f, s1 = 0.f;
        #pragma unroll
        for (int j = 0; j < 8; ++j) {
            c[j][0] = __expf(c[j][0] - mn0);
            c[j][1] = __expf(c[j][1] - mn0);
            c[j][2] = __expf(c[j][2] - mn1);
            c[j][3] = __expf(c[j][3] - mn1);
            s0 += c[j][0] + c[j][1];
            s1 += c[j][2] + c[j][3];
        }
        s0 += __shfl_xor_sync(0xffffffffu, s0, 1);
        s0 += __shfl_xor_sync(0xffffffffu, s0, 2);
        s1 += __shfl_xor_sync(0xffffffffu, s1, 1);
        s1 += __shfl_xor_sync(0xffffffffu, s1, 2);
        l0 = l0 * al0 + s0;
        l1 = l1 * al1 + s1;
        #pragma unroll
        for (int j = 0; j < 8; ++j) {
            O[j][0] *= al0; O[j][1] *= al0;
            O[j][2] *= al1; O[j][3] *= al1;
        }
        m0 = mn0; m1 = mn1;

        #pragma unroll
        for (int ms = 0; ms < 4; ++ms) {
            float ph[8], pl[8];
            #pragma unroll
            for (int e = 0; e < 4; ++e) {
                float v0 = c[2 * ms][e];
                float v1 = c[2 * ms + 1][e];
                __nv_bfloat16 h0 = __float2bfloat16(v0);
                __nv_bfloat16 h1 = __float2bfloat16(v1);
                ph[e] = __bfloat162float(h0);
                ph[4 + e] = __bfloat162float(h1);
                pl[e] = v0 - ph[e];
                pl[4 + e] = v1 - ph[4 + e];
            }
            uint32_t ah[4], al[4];
            ah[0] = packbf(ph[0], ph[1]); ah[1] = packbf(ph[2], ph[3]);
            ah[2] = packbf(ph[4], ph[5]); ah[3] = packbf(ph[6], ph[7]);
            al[0] = packbf(pl[0], pl[1]); al[1] = packbf(pl[2], pl[3]);
            al[2] = packbf(pl[4], pl[5]); al[3] = packbf(pl[6], pl[7]);
            uint32_t vaddr = v_roff + ms * 16 * 144;
            #pragma unroll
            for (int jp = 0; jp < 4; ++jp) {
                uint32_t vh[4], vl[4];
                ldsm4t(vh, sVh + vaddr + jp * 32);
                ldsm4t(vl, sVl + vaddr + jp * 32);
                mma16816(O[jp * 2],     ah, vh);
                mma16816(O[jp * 2 + 1], ah, vh + 2);
                mma16816(O[jp * 2],     al, vh);
                mma16816(O[jp * 2 + 1], al, vh + 2);
                mma16816(O[jp * 2],     ah, vl);
                mma16816(O[jp * 2 + 1], ah, vl + 2);
            }
        }
    }

    __syncthreads();
    float* Of = (float*)sm_;
    float i0 = 1.f / l0, i1 = 1.f / l1;
    #pragma unroll
    for (int j = 0; j < 8; ++j) {
        int cc = j * 8 + tg * 2;
        Of[(wr0 + g) * 66 + cc]     = O[j][0] * i0;
        Of[(wr0 + g) * 66 + cc + 1] = O[j][1] * i0;
        Of[(wr0 + g + 8) * 66 + cc]     = O[j][2] * i1;
        Of[(wr0 + g + 8) * 66 + cc + 1] = O[j][3] * i1;
    }
    __syncthreads();
    #pragma unroll
    for (int i = 0; i < 16; ++i) {
        int idx2 = tid + i * 256;
        int r = idx2 >> 5, c2 = (idx2 & 31) * 2;
        float v0 = Of[r * 66 + c2], v1 = Of[r * 66 + c2 + 1];
        __nv_bfloat16 h0 = __float2bfloat16(v0);
        __nv_bfloat16 h1 = __float2bfloat16(v1);
        __nv_bfloat16 lo0 = __float2bfloat16(v0 - __bfloat162float(h0));
        __nv_bfloat16 lo1 = __float2bfloat16(v1 - __bfloat162float(h1));
        int tok = b * T_ + qt * 128 + r;
        size_t base = (size_t)tok * 3072 + h * 64 + c2;
        *(__nv_bfloat162*)(exo + base)        = __nv_bfloat162(h0, h1);
        *(__nv_bfloat162*)(exo + base + 1024) = __nv_bfloat162(lo0, lo1);
        *(__nv_bfloat162*)(exo + base + 2048) = __nv_bfloat162(h0, h1);
    }
}

// ---------------- reductions / prep ----------------
__device__ __forceinline__ float2 block_reduce2(float a, float b) {
    #pragma unroll
    for (int o = 16; o; o >>= 1) {
        a += __shfl_xor_sync(0xffffffffu, a, o);
        b += __shfl_xor_sync(0xffffffffu, b, o);
    }
    __shared__ float sa[8], sb2[8];
    int w = threadIdx.x >> 5, l = threadIdx.x & 31;
    int nw = (blockDim.x + 31) >> 5;
    if (l == 0) { sa[w] = a; sb2[w] = b; }
    __syncthreads();
    if (w == 0) {
        a = (l < nw) ? sa[l] : 0.f;
        b = (l < nw) ? sb2[l] : 0.f;
        #pragma unroll
        for (int o = 4; o; o >>= 1) {
            a += __shfl_xor_sync(0xffffffffu, a, o);
            b += __shfl_xor_sync(0xffffffffu, b, o);
        }
        if (l == 0) { sa[0] = a; sb2[0] = b; }
    }
    __syncthreads();
    return make_float2(sa[0], sb2[0]);
}

__global__ void reset_k() {
    if (threadIdx.x < 8) g_maxabs[threadIdx.x] = 0u;
}

__global__ __launch_bounds__(256) void absmax_all(const float* wq, const float* wk,
                                                  const float* wv, const float* wo,
                                                  const float* su, const float* sv,
                                                  const float* wup, const float* wdn) {
    int seg = blockIdx.x >> 8, blk = blockIdx.x & 255;
    const float* p; int n;
    switch (seg) {
        case 0: p = wq;  n = D_ * D_;   break;
        case 1: p = wk;  n = D_ * D_;   break;
        case 2: p = wv;  n = D_ * D_;   break;
        case 3: p = wo;  n = D_ * D_;   break;
        case 4: p = su;  n = S_ * S_;   break;
        case 5: p = sv;  n = S_ * S_;   break;
        case 6: p = wup; n = HID_ * D_; break;
        default: p = wdn; n = HID_ * D_; break;
    }
    float m = 0.f;
    for (int i = blk * 256 + threadIdx.x; i < n; i += 256 * 256)
        m = fmaxf(m, fabsf(p[i]));
    #pragma unroll
    for (int o = 16; o; o >>= 1) m = fmaxf(m, __shfl_xor_sync(0xffffffffu, m, o));
    __shared__ float sm[8];
    if ((threadIdx.x & 31) == 0) sm[threadIdx.x >> 5] = m;
    __syncthreads();
    if (threadIdx.x < 8) {
        m = sm[threadIdx.x];
        #pragma unroll
        for (int o = 4; o; o >>= 1) m = fmaxf(m, __shfl_xor_sync(0xffu, m, o));
        if (threadIdx.x == 0) atomicMax(&g_maxabs[seg], __float_as_uint(m));
    }
}

// quantize + B-side split [hi|hi|lo], with destination row offset
__global__ __launch_bounds__(256) void quant_split_k(const float* __restrict__ w,
                                                     __nv_bfloat16* __restrict__ out,
                                                     int K, int slot, int total, int rowoff) {
    float scale = __uint_as_float(g_maxabs[slot]) / 31.0f + 1e-8f;
    int idx = blockIdx.x * blockDim.x + threadIdx.x;
    if (idx >= total) return;
    int n = idx / K, k = idx - n * K;
    float q = rintf(w[idx] / scale);
    q = fminf(fmaxf(q, -31.f), 31.f);
    float x = q * scale;
    __nv_bfloat16 h = __float2bfloat16(x);
    __nv_bfloat16 l = __float2bfloat16(x - __bfloat162float(h));
    size_t base = (size_t)(n + rowoff) * (3 * K) + k;
    out[base] = h; out[base + K] = h; out[base + 2 * K] = l;
}

// plain B-side split (pre-fused fp32 input)
__global__ __launch_bounds__(256) void split_b_k(const float* __restrict__ in,
                                                 __nv_bfloat16* __restrict__ out,
                                                 int K, int total, int rowoff) {
    int idx = blockIdx.x * blockDim.x + threadIdx.x;
    if (idx >= total) return;
    int n = idx / K, k = idx - n * K;
    float x = in[idx];
    __nv_bfloat16 h = __float2bfloat16(x);
    __nv_bfloat16 l = __float2bfloat16(x - __bfloat162float(h));
    size_t base = (size_t)(n + rowoff) * (3 * K) + k;
    out[base] = h; out[base + K] = h; out[base + 2 * K] = l;
}

// fw[h*64+s][k] = sum_j q(su)[s][j] * q(w)[h*64+j][k]  (quantization fused in)
__global__ __launch_bounds__(256) void fuse_stalk_q(const float* __restrict__ su,
                                                    const float* __restrict__ w,
                                                    float* __restrict__ fw,
                                                    int slot_s, int slot_w) {
    __shared__ float Ws[64][128];
    __shared__ float Ss[64][64];
    float sc_s = __uint_as_float(g_maxabs[slot_s]) / 31.0f + 1e-8f;
    float sc_w = __uint_as_float(g_maxabs[slot_w]) / 31.0f + 1e-8f;
    int h = blockIdx.y;
    int k0 = blockIdx.x * 128;
    int tid = threadIdx.x;
    #pragma unroll
    for (int it = 0; it < 8; ++it) {
        int chunk = tid + it * 256;
        int r = chunk >> 5, c4 = (chunk & 31) * 4;
        float4 v = *(const float4*)(w + (size_t)(h * 64 + r) * D_ + k0 + c4);
        Ws[r][c4 + 0] = fminf(fmaxf(rintf(v.x / sc_w), -31.f), 31.f) * sc_w;
        Ws[r][c4 + 1] = fminf(fmaxf(rintf(v.y / sc_w), -31.f), 31.f) * sc_w;
        Ws[r][c4 + 2] = fminf(fmaxf(rintf(v.z / sc_w), -31.f), 31.f) * sc_w;
        Ws[r][c4 + 3] = fminf(fmaxf(rintf(v.w / sc_w), -31.f), 31.f) * sc_w;
    }
    #pragma unroll
    for (int it = 0; it < 4; ++it) {
        int chunk = tid + it * 256;
        int r = chunk >> 4, c4 = (chunk & 15) * 4;
        float4 v = *(const float4*)(su + (size_t)r * 64 + c4);
        Ss[r][c4 + 0] = fminf(fmaxf(rintf(v.x / sc_s), -31.f), 31.f) * sc_s;
        Ss[r][c4 + 1] = fminf(fmaxf(rintf(v.y / sc_s), -31.f), 31.f) * sc_s;
        Ss[r][c4 + 2] = fminf(fmaxf(rintf(v.z / sc_s), -31.f), 31.f) * sc_s;
        Ss[r][c4 + 3] = fminf(fmaxf(rintf(v.w / sc_s), -31.f), 31.f) * sc_s;
    }
    __syncthreads();
    #pragma unroll 4
    for (int it = 0; it < 32; ++it) {
        int oidx = tid + it * 256;
        int s = oidx >> 7, kk = oidx & 127;
        float acc = 0.f;
        #pragma unroll
        for (int j = 0; j < 64; ++j) acc += Ss[s][j] * Ws[j][kk];
        fw[(size_t)(h * 64 + s) * D_ + k0 + kk] = acc;
    }
}

// layernorm(D) + A-side split [hi|lo|hi]
__global__ __launch_bounds__(256) void ln_split_k(const float* __restrict__ x,
                                                  const float* __restrict__ g,
                                                  const float* __restrict__ bb,
                                                  __nv_bfloat16* __restrict__ out) {
    int row = blockIdx.x;
    const float* xr = x + (size_t)row * D_;
    int c = threadIdx.x * 4;
    float4 v = *(const float4*)(xr + c);
    float s = v.x + v.y + v.z + v.w;
    float sq = v.x * v.x + v.y * v.y + v.z * v.z + v.w * v.w;
    float2 r = block_reduce2(s, sq);
    float mu = r.x * (1.0f / D_);
    float var = r.y * (1.0f / D_) - mu * mu;
    float inv = rsqrtf(var + 1e-5f);
    float4 gg = *(const float4*)(g + c);
    float4 bv = *(const float4*)(bb + c);
    float o[4];
    o[0] = (v.x - mu) * inv * gg.x + bv.x;
    o[1] = (v.y - mu) * inv * gg.y + bv.y;
    o[2] = (v.z - mu) * inv * gg.z + bv.z;
    o[3] = (v.w - mu) * inv * gg.w + bv.w;
    size_t base = (size_t)row * 3072 + c;
    #pragma unroll
    for (int p2 = 0; p2 < 2; ++p2) {
        float a0 = o[p2 * 2], a1 = o[p2 * 2 + 1];
        __nv_bfloat16 h0 = __float2bfloat16(a0), h1 = __float2bfloat16(a1);
        __nv_bfloat16 l0 = __float2bfloat16(a0 - __bfloat162float(h0));
        __nv_bfloat16 l1 = __float2bfloat16(a1 - __bfloat162float(h1));
        *(__nv_bfloat162*)(out + base + p2 * 2)        = __nv_bfloat162(h0, h1);
        *(__nv_bfloat162*)(out + base + 1024 + p2 * 2) = __nv_bfloat162(l0, l1);
        *(__nv_bfloat162*)(out + base + 2048 + p2 * 2) = __nv_bfloat162(h0, h1);
    }
}

// SO(2) rotate + layernorm(HID) + SiLU + A-side split
__global__ __launch_bounds__(256) void rot_split_k(const float* __restrict__ hin,
                                                   const float* __restrict__ theta,
                                                   const float* __restrict__ g,
                                                   const float* __restrict__ bb,
                                                   __nv_bfloat16* __restrict__ out) {
    int row = blockIdx.x;
    const float* hrow = hin + (size_t)row * HID_;
    int tid = threadIdx.x;
    float r0[6], r1[6];
    float s = 0.f, sq = 0.f;
    #pragma unroll
    for (int i = 0; i < 6; ++i) {
        int p = tid + i * 256;
        float2 ab = *(const float2*)(hrow + 2 * p);
        float sn, cs;
        sincosf(theta[p], &sn, &cs);
        r0[i] = cs * ab.x - sn * ab.y;
        r1[i] = sn * ab.x + cs * ab.y;
        s += r0[i] + r1[i];
        sq += r0[i] * r0[i] + r1[i] * r1[i];
    }
    float2 r = block_reduce2(s, sq);
    float mu = r.x * (1.0f / HID_);
    float var = r.y * (1.0f / HID_) - mu * mu;
    float inv = rsqrtf(var + 1e-5f);
    size_t base = (size_t)row * (3 * HID_);
    #pragma unroll
    for (int i = 0; i < 6; ++i) {
        int p = tid + i * 256;
        int e0 = 2 * p, e1 = 2 * p + 1;
        float y0 = (r0[i] - mu) * inv * g[e0] + bb[e0];
        float y1 = (r1[i] - mu) * inv * g[e1] + bb[e1];
        y0 = y0 / (1.0f + __expf(-y0));
        y1 = y1 / (1.0f + __expf(-y1));
        __nv_bfloat16 h0 = __float2bfloat16(y0), h1 = __float2bfloat16(y1);
        __nv_bfloat16 l0 = __float2bfloat16(y0 - __bfloat162float(h0));
        __nv_bfloat16 l1 = __float2bfloat16(y1 - __bfloat162float(h1));
        *(__nv_bfloat162*)(out + base + e0)            = __nv_bfloat162(h0, h1);
        *(__nv_bfloat162*)(out + base + HID_ + e0)     = __nv_bfloat162(l0, l1);
        *(__nv_bfloat162*)(out + base + 2 * HID_ + e0) = __nv_bfloat162(h0, h1);
    }
}

// ---------------- host launcher ----------------
extern "C" void kernel_launch(void* const* d_in, const int* in_sizes, int n_in,
                              void* d_out, int out_size) {
    const float* x   = (const float*)d_in[0];
    const float* wq  = (const float*)d_in[1];
    const float* wk  = (const float*)d_in[2];
    const float* wv  = (const float*)d_in[3];
    const float* wo  = (const float*)d_in[4];
    const float* su  = (const float*)d_in[5];
    const float* sv  = (const float*)d_in[6];
    const float* ps  = (const float*)d_in[7];
    const float* n1g = (const float*)d_in[8];
    const float* n1b = (const float*)d_in[9];
    const float* n2g = (const float*)d_in[10];
    const float* n2b = (const float*)d_in[11];
    const float* wup = (const float*)d_in[12];
    const float* wdn = (const float*)d_in[13];
    const float* th  = (const float*)d_in[14];
    const float* mng = (const float*)d_in[15];
    const float* mnb = (const float*)d_in[16];
    float* out = (float*)d_out;

    float *fwq, *fwk, *hb;
    __nv_bfloat16 *ex, *eh, *eqkv, *ewo, *eup, *edn;
    cudaGetSymbolAddress((void**)&fwq, g_fwq);
    cudaGetSymbolAddress((void**)&fwk, g_fwk);
    cudaGetSymbolAddress((void**)&hb, g_h);
    cudaGetSymbolAddress((void**)&ex, e_x);
    cudaGetSymbolAddress((void**)&eh, e_h);
    cudaGetSymbolAddress((void**)&eqkv, e_qkv);
    cudaGetSymbolAddress((void**)&ewo, e_wo);
    cudaGetSymbolAddress((void**)&eup, e_up);
    cudaGetSymbolAddress((void**)&edn, e_dn);

    static bool attr_set = false;
    if (!attr_set) {
        cudaFuncSetAttribute(mm_hmma, cudaFuncAttributeMaxDynamicSharedMemorySize, MMX_SMEM);
        cudaFuncSetAttribute(flash_k, cudaFuncAttributeMaxDynamicSharedMemorySize, FL_SMEM);
        attr_set = true;
    }

    const int nDD = D_ * D_;
    const int nUP = HID_ * D_;

    // weight prep
    reset_k<<<1, 32>>>();
    absmax_all<<<2048, 256>>>(wq, wk, wv, wo, su, sv, wup, wdn);
    fuse_stalk_q<<<dim3(D_ / 128, H_), 256>>>(su, wq, fwq, 4, 0);
    fuse_stalk_q<<<dim3(D_ / 128, H_), 256>>>(sv, wk, fwk, 5, 1);
    split_b_k<<<(nDD + 255) / 256, 256>>>(fwq, eqkv, D_, nDD, 0);
    split_b_k<<<(nDD + 255) / 256, 256>>>(fwk, eqkv, D_, nDD, 1024);
    quant_split_k<<<(nDD + 255) / 256, 256>>>(wv, eqkv, D_, 2, nDD, 2048);
    quant_split_k<<<(nDD + 255) / 256, 256>>>(wo, ewo, D_, 3, nDD, 0);
    quant_split_k<<<(nUP + 255) / 256, 256>>>(wup, eup, D_, 6, nUP, 0);
    quant_split_k<<<(nUP + 255) / 256, 256>>>(wdn, edn, HID_, 7, nUP, 0);

    // attention half
    ln_split_k<<<NTOK, 256>>>(x, n1g, n1b, ex);
    mm_hmma<<<dim3(12, 32), 256, MMX_SMEM>>>(ex, eqkv, nullptr, hb, NTOK, 3 * D_, 3 * D_);
    flash_k<<<dim3(8, 64), 256, FL_SMEM>>>(hb, ps, ex);
    mm_hmma<<<dim3(4, 32), 256, MMX_SMEM>>>(ex, ewo, x, out, NTOK, D_, 3 * D_);

    // MLP half
    ln_split_k<<<NTOK, 256>>>(out, n2g, n2b, ex);
    mm_hmma<<<dim3(12, 32), 256, MMX_SMEM>>>(ex, eup, nullptr, hb, NTOK, HID_, 3 * D_);
    rot_split_k<<<NTOK, 256>>>(hb, th, mng, mnb, eh);
    mm_hmma<<<dim3(4, 32), 256, MMX_SMEM>>>(eh, edn, out, out, NTOK, D_, 3 * HID_);
}

// round 9
// speedup vs baseline: 1.4085x; 1.4085x over previous
#include <cuda_runtime.h>
#include <cuda_fp16.h>
#include <math.h>
#include <stdint.h>

// ---------------- problem constants ----------------
#define B_ 4
#define T_ 1024
#define D_ 1024
#define H_ 16
#define S_ 64
#define HID_ 3072
#define NTOK (B_*T_)            // 4096

// ---------------- device scratch ----------------
__device__ float g_fwq[D_*D_];
__device__ float g_fwk[D_*D_];
__device__ float g_h[(size_t)NTOK*HID_];            // QKV output, then MLP hidden (fp32)
__device__ unsigned g_maxabs[8];

// fp16 2-term split buffers (A-side: [hi|lo], B-side: [hi|hi])
__device__ __half e_x  [(size_t)NTOK*2*D_];        // activations A-side
__device__ __half e_h  [(size_t)NTOK*2*HID_];      // mlp hidden A-side
__device__ __half e_qkv[(size_t)(3*D_)*2*D_];      // fused QKV weights B-side
__device__ __half e_wo [(size_t)D_*2*D_];
__device__ __half e_up [(size_t)HID_*2*D_];
__device__ __half e_dn [(size_t)D_*2*HID_];

// ---------------- PTX helpers ----------------
__device__ __forceinline__ uint32_t s2u(const void* p) {
    uint32_t a;
    asm("{ .reg .u64 t; cvta.to.shared.u64 t, %1; cvt.u32.u64 %0, t; }" : "=r"(a) : "l"(p));
    return a;
}
__device__ __forceinline__ void ldsm4(uint32_t* r, uint32_t a) {
    asm volatile("ldmatrix.sync.aligned.m8n8.x4.shared.b16 {%0,%1,%2,%3}, [%4];"
        : "=r"(r[0]), "=r"(r[1]), "=r"(r[2]), "=r"(r[3]) : "r"(a));
}
__device__ __forceinline__ void ldsm4t(uint32_t* r, uint32_t a) {
    asm volatile("ldmatrix.sync.aligned.m8n8.x4.trans.shared.b16 {%0,%1,%2,%3}, [%4];"
        : "=r"(r[0]), "=r"(r[1]), "=r"(r[2]), "=r"(r[3]) : "r"(a));
}
__device__ __forceinline__ void ldsm2(uint32_t* r, uint32_t a) {
    asm volatile("ldmatrix.sync.aligned.m8n8.x2.shared.b16 {%0,%1}, [%2];"
        : "=r"(r[0]), "=r"(r[1]) : "r"(a));
}
__device__ __forceinline__ void mma16816(float* c, const uint32_t* a, const uint32_t* b) {
    asm volatile("mma.sync.aligned.m16n8k16.row.col.f32.f16.f16.f32 "
        "{%0,%1,%2,%3}, {%4,%5,%6,%7}, {%8,%9}, {%0,%1,%2,%3};"
        : "+f"(c[0]), "+f"(c[1]), "+f"(c[2]), "+f"(c[3])
        : "r"(a[0]), "r"(a[1]), "r"(a[2]), "r"(a[3]), "r"(b[0]), "r"(b[1]));
}
__device__ __forceinline__ void cpasync16(uint32_t dst, const void* src) {
    asm volatile("cp.async.cg.shared.global [%0], [%1], 16;" :: "r"(dst), "l"(src));
}
__device__ __forceinline__ uint32_t packh(float lo, float hi) {
    uint32_t r;
    asm("cvt.rn.f16x2.f32 %0, %1, %2;" : "=r"(r) : "f"(hi), "f"(lo));
    return r;
}

// ---------------- fp16 HMMA GEMM: C[M,N] = A[M,K2] @ B[N,K2]^T (+Res) ----------------
// CTA tile 128x128, 8 warps (2x4), warp tile 64x32, K-chunk 64, double-buffered cp.async.
#define MMX_SMEM 65536
__global__ __launch_bounds__(256) void mm_hmma(const __half* __restrict__ Ag,
                                               const __half* __restrict__ Bg,
                                               const float* __restrict__ Res,
                                               float* __restrict__ C,
                                               int M, int N, int K2) {
    extern __shared__ char sm_[];
    uint32_t sbase = s2u(sm_);
    int tid = threadIdx.x, lane = tid & 31, wid = tid >> 5;
    int wm = wid >> 2, wn = wid & 3;
    int m0 = blockIdx.y * 128, n0 = blockIdx.x * 128;
    const __half* Ap = Ag + (size_t)m0 * K2;
    const __half* Bp = Bg + (size_t)n0 * K2;
    int NC = K2 >> 6;

    float c[4][4][4];
    #pragma unroll
    for (int i = 0; i < 4; ++i)
        #pragma unroll
        for (int j = 0; j < 4; ++j)
            #pragma unroll
            for (int e = 0; e < 4; ++e) c[i][j][e] = 0.f;

    int crow = tid >> 3, cch = tid & 7;

    #define COPY_CHUNK(cidx, buf) do {                                             \
        uint32_t Ab_ = sbase + (buf) * 32768;                                      \
        uint32_t Bb_ = Ab_ + 16384;                                                \
        int kc_ = (cidx) << 6;                                                     \
        _Pragma("unroll")                                                          \
        for (int i_ = 0; i_ < 4; ++i_) {                                           \
            int row_ = crow + i_ * 32;                                             \
            uint32_t dst_ = Ab_ + row_ * 128 + (((cch) ^ (row_ & 7)) << 4);        \
            cpasync16(dst_, Ap + (size_t)row_ * K2 + kc_ + cch * 8);               \
        }                                                                          \
        _Pragma("unroll")                                                          \
        for (int i_ = 0; i_ < 4; ++i_) {                                           \
            int row_ = crow + i_ * 32;                                             \
            uint32_t dst_ = Bb_ + row_ * 128 + (((cch) ^ (row_ & 7)) << 4);        \
            cpasync16(dst_, Bp + (size_t)row_ * K2 + kc_ + cch * 8);               \
        }                                                                          \
        asm volatile("cp.async.commit_group;" ::: "memory");                       \
    } while (0)

    COPY_CHUNK(0, 0);
    for (int c0 = 0; c0 < NC; ++c0) {
        int buf = c0 & 1;
        if (c0 + 1 < NC) {
            COPY_CHUNK(c0 + 1, buf ^ 1);
            asm volatile("cp.async.wait_group 1;" ::: "memory");
        } else {
            asm volatile("cp.async.wait_group 0;" ::: "memory");
        }
        __syncthreads();
        uint32_t Ab = sbase + buf * 32768;
        uint32_t Bb = Ab + 16384;
        #pragma unroll
        for (int ks = 0; ks < 4; ++ks) {
            uint32_t a[4][4], b[4][2];
            #pragma unroll
            for (int i = 0; i < 4; ++i) {
                int row = wm * 64 + i * 16 + (lane & 15);
                int ch = ks * 2 + (lane >> 4);
                ldsm4(a[i], Ab + row * 128 + ((ch ^ (row & 7)) << 4));
            }
            #pragma unroll
            for (int j = 0; j < 4; ++j) {
                int row = wn * 32 + j * 8 + (lane & 7);
                int ch = ks * 2 + ((lane >> 3) & 1);
                ldsm2(b[j], Bb + row * 128 + ((ch ^ (row & 7)) << 4));
            }
            #pragma unroll
            for (int i = 0; i < 4; ++i)
                #pragma unroll
                for (int j = 0; j < 4; ++j)
                    mma16816(c[i][j], a[i], b[j]);
        }
        __syncthreads();
    }
    #undef COPY_CHUNK

    int g = lane >> 2, tg = lane & 3;
    #pragma unroll
    for (int i = 0; i < 4; ++i) {
        int r0 = m0 + wm * 64 + i * 16 + g;
        #pragma unroll
        for (int j = 0; j < 4; ++j) {
            int cc = n0 + wn * 32 + j * 8 + tg * 2;
            float* p0 = C + (size_t)r0 * N + cc;
            float* p1 = C + (size_t)(r0 + 8) * N + cc;
            if (Res) {
                float2 v0 = *(const float2*)(Res + (size_t)r0 * N + cc);
                float2 v1 = *(const float2*)(Res + (size_t)(r0 + 8) * N + cc);
                *(float2*)p0 = make_float2(c[i][j][0] + v0.x, c[i][j][1] + v0.y);
                *(float2*)p1 = make_float2(c[i][j][2] + v1.x, c[i][j][3] + v1.y);
            } else {
                *(float2*)p0 = make_float2(c[i][j][0], c[i][j][1]);
                *(float2*)p1 = make_float2(c[i][j][2], c[i][j][3]);
            }
        }
    }
}

// ---------------- fused flash attention (fp16 2-term) ----------------
// smem: Qs[128][136] Ks[64][136] Vh[64][72] fp16  (61440 B)
#define FL_SMEM 61440
__global__ __launch_bounds__(256, 2) void flash_k(const float* __restrict__ qkv,
                                                  const float* __restrict__ p_scale,
                                                  __half* __restrict__ exo) {
    extern __shared__ char sm_[];
    uint32_t sb = s2u(sm_);
    const uint32_t sQ = sb, sK = sb + 34816, sVh = sb + 52224;
    __half* Qs = (__half*)sm_;
    __half* Ks = (__half*)(sm_ + 34816);
    __half* Vh = (__half*)(sm_ + 52224);

    int tid = threadIdx.x, lane = tid & 31, wid = tid >> 5;
    int qt = 7 - (int)blockIdx.x;               // big tiles first
    int bh = blockIdx.y, b = bh >> 4, h = bh & 15;

    const float* Qg = qkv + ((size_t)(b * T_ + qt * 128)) * 3072 + h * 64;
    const float* Kg = qkv + (size_t)(b * T_) * 3072 + 1024 + h * 64;
    const float* Vg = qkv + (size_t)(b * T_) * 3072 + 2048 + h * 64;

    // load + split Q (128x64 fp32 -> [hi|lo] fp16, pitch 136)
    #pragma unroll
    for (int i = 0; i < 8; ++i) {
        int idx = tid + i * 256;
        int r = idx >> 4, c4 = (idx & 15) * 4;
        float4 v = *(const float4*)(Qg + (size_t)r * 3072 + c4);
        float vv[4] = {v.x, v.y, v.z, v.w};
        #pragma unroll
        for (int j = 0; j < 4; ++j) {
            __half hi = __float2half(vv[j]);
            __half lo = __float2half(vv[j] - __half2float(hi));
            Qs[r * 136 + c4 + j] = hi;
            Qs[r * 136 + 64 + c4 + j] = lo;
        }
    }

    float m0 = -INFINITY, m1 = -INFINITY, l0 = 0.f, l1 = 0.f;
    float O[8][4];
    #pragma unroll
    for (int j = 0; j < 8; ++j)
        #pragma unroll
        for (int e = 0; e < 4; ++e) O[j][e] = 0.f;

    float ps = p_scale[0];
    int g = lane >> 2, tg = lane & 3;
    int wr0 = wid * 16;
    int row_g0 = qt * 128 + wr0 + g;
    int nch = (qt * 128 + 128) >> 6;

    uint32_t aq_base = sQ + (wr0 + (lane & 15)) * 272 + (lane >> 4) * 16;
    uint32_t bk_base = sK + (((lane >> 3) & 2) * 4 + (lane & 7)) * 272 + ((lane >> 3) & 1) * 16;
    uint32_t v_roff = ((lane & 7) + ((lane >> 3) & 1) * 8) * 144 + ((lane >> 4) & 1) * 16;

    for (int ch = 0; ch < nch; ++ch) {
        int u0 = ch << 6;
        __syncthreads();
        // load + split K (2 segs hi|hi) and V (hi only) chunk (64x64 fp32 each)
        #pragma unroll
        for (int i = 0; i < 4; ++i) {
            int idx = tid + i * 256;
            int r = idx >> 4, c4 = (idx & 15) * 4;
            float4 kv = *(const float4*)(Kg + (size_t)(u0 + r) * 3072 + c4);
            float4 vv = *(const float4*)(Vg + (size_t)(u0 + r) * 3072 + c4);
            float ka[4] = {kv.x, kv.y, kv.z, kv.w};
            float va[4] = {vv.x, vv.y, vv.z, vv.w};
            #pragma unroll
            for (int j = 0; j < 4; ++j) {
                __half khi = __float2half(ka[j]);
                Ks[r * 136 + c4 + j] = khi;
                Ks[r * 136 + 64 + c4 + j] = khi;
                Vh[r * 72 + c4 + j] = __float2half(va[j]);
            }
        }
        __syncthreads();

        // S = Q @ K^T (K'=128 split)
        float c[8][4];
        #pragma unroll
        for (int j = 0; j < 8; ++j)
            #pragma unroll
            for (int e = 0; e < 4; ++e) c[j][e] = 0.f;
        #pragma unroll
        for (int ks = 0; ks < 8; ++ks) {
            uint32_t a[4];
            ldsm4(a, aq_base + ks * 32);
            #pragma unroll
            for (int jp = 0; jp < 4; ++jp) {
                uint32_t bb[4];
                ldsm4(bb, bk_base + jp * 16 * 272 + ks * 32);
                mma16816(c[jp * 2], a, bb);
                mma16816(c[jp * 2 + 1], a, bb + 2);
            }
        }

        // scale + p-adic bias + causal mask
        #pragma unroll
        for (int j = 0; j < 8; ++j) {
            int ub = u0 + j * 8 + tg * 2;
            #pragma unroll
            for (int e = 0; e < 4; ++e) {
                int row = row_g0 + (e >> 1) * 8;
                int u = ub + (e & 1);
                int d = row - u;
                if (d < 0) c[j][e] = -INFINITY;
                else {
                    float bias;
                    if (d == 0) bias = 1.f;
                    else {
                        int vp = __ffs(d) - 1;
                        vp = vp > 16 ? 16 : vp;
                        bias = (float)vp * (1.f / 16.f);
                    }
                    c[j][e] = c[j][e] * 0.125f + ps * bias;
                }
            }
        }

        // online softmax
        float mx0 = -INFINITY, mx1 = -INFINITY;
        #pragma unroll
        for (int j = 0; j < 8; ++j) {
            mx0 = fmaxf(mx0, fmaxf(c[j][0], c[j][1]));
            mx1 = fmaxf(mx1, fmaxf(c[j][2], c[j][3]));
        }
        mx0 = fmaxf(mx0, __shfl_xor_sync(0xffffffffu, mx0, 1));
        mx0 = fmaxf(mx0, __shfl_xor_sync(0xffffffffu, mx0, 2));
        mx1 = fmaxf(mx1, __shfl_xor_sync(0xffffffffu, mx1, 1));
        mx1 = fmaxf(mx1, __shfl_xor_sync(0xffffffffu, mx1, 2));
        float mn0 = fmaxf(m0, mx0), mn1 = fmaxf(m1, mx1);
        float al0 = __expf(m0 - mn0), al1 = __expf(m1 - mn1);
        float s0 = 0.f, s1 = 0.f;
        #pragma unroll
        for (int j = 0; j < 8; ++j) {
            c[j][0] = __expf(c[j][0] - mn0);
            c[j][1] = __expf(c[j][1] - mn0);
            c[j][2] = __expf(c[j][2] - mn1);
            c[j][3] = __expf(c[j][3] - mn1);
            s0 += c[j][0] + c[j][1];
            s1 += c[j][2] + c[j][3];
        }
        s0 += __shfl_xor_sync(0xffffffffu, s0, 1);
        s0 += __shfl_xor_sync(0xffffffffu, s0, 2);
        s1 += __shfl_xor_sync(0xffffffffu, s1, 1);
        s1 += __shfl_xor_sync(0xffffffffu, s1, 2);
        l0 = l0 * al0 + s0;
        l1 = l1 * al1 + s1;
        #pragma unroll
        for (int j = 0; j < 8; ++j) {
            O[j][0] *= al0; O[j][1] *= al0;
            O[j][2] *= al1; O[j][3] *= al1;
        }
        m0 = mn0; m1 = mn1;

        // O += P @ V  (P = Ph + Pl 2-term; V hi only)
        #pragma unroll
        for (int ms = 0; ms < 4; ++ms) {
            float ph[8], pl[8];
            #pragma unroll
            for (int e = 0; e < 4; ++e) {
                float v0 = c[2 * ms][e];
                float v1 = c[2 * ms + 1][e];
                __half h0 = __float2half(v0);
                __half h1 = __float2half(v1);
                ph[e] = __half2float(h0);
                ph[4 + e] = __half2float(h1);
                pl[e] = v0 - ph[e];
                pl[4 + e] = v1 - ph[4 + e];
            }
            uint32_t ah[4], al[4];
            ah[0] = packh(ph[0], ph[1]); ah[1] = packh(ph[2], ph[3]);
            ah[2] = packh(ph[4], ph[5]); ah[3] = packh(ph[6], ph[7]);
            al[0] = packh(pl[0], pl[1]); al[1] = packh(pl[2], pl[3]);
            al[2] = packh(pl[4], pl[5]); al[3] = packh(pl[6], pl[7]);
            uint32_t vaddr = v_roff + ms * 16 * 144;
            #pragma unroll
            for (int jp = 0; jp < 4; ++jp) {
                uint32_t vh[4];
                ldsm4t(vh, sVh + vaddr + jp * 32);
                mma16816(O[jp * 2],     ah, vh);
                mma16816(O[jp * 2 + 1], ah, vh + 2);
                mma16816(O[jp * 2],     al, vh);
                mma16816(O[jp * 2 + 1], al, vh + 2);
            }
        }
    }

    // epilogue: stage fp32 O in smem, then coalesced [hi|lo] write
    __syncthreads();
    float* Of = (float*)sm_;        // [128][66]
    float i0 = 1.f / l0, i1 = 1.f / l1;
    #pragma unroll
    for (int j = 0; j < 8; ++j) {
        int cc = j * 8 + tg * 2;
        Of[(wr0 + g) * 66 + cc]     = O[j][0] * i0;
        Of[(wr0 + g) * 66 + cc + 1] = O[j][1] * i0;
        Of[(wr0 + g + 8) * 66 + cc]     = O[j][2] * i1;
        Of[(wr0 + g + 8) * 66 + cc + 1] = O[j][3] * i1;
    }
    __syncthreads();
    #pragma unroll
    for (int i = 0; i < 16; ++i) {
        int idx2 = tid + i * 256;              // 4096 half2 units
        int r = idx2 >> 5, c2 = (idx2 & 31) * 2;
        float v0 = Of[r * 66 + c2], v1 = Of[r * 66 + c2 + 1];
        __half h0 = __float2half(v0);
        __half h1 = __float2half(v1);
        __half lo0 = __float2half(v0 - __half2float(h0));
        __half lo1 = __float2half(v1 - __half2float(h1));
        int tok = b * T_ + qt * 128 + r;
        size_t base = (size_t)tok * 2048 + h * 64 + c2;
        *(__half2*)(exo + base)        = __halves2half2(h0, h1);
        *(__half2*)(exo + base + 1024) = __halves2half2(lo0, lo1);
    }
}

// ---------------- reductions / prep ----------------
__device__ __forceinline__ float2 block_reduce2(float a, float b) {
    #pragma unroll
    for (int o = 16; o; o >>= 1) {
        a += __shfl_xor_sync(0xffffffffu, a, o);
        b += __shfl_xor_sync(0xffffffffu, b, o);
    }
    __shared__ float sa[8], sb2[8];
    int w = threadIdx.x >> 5, l = threadIdx.x & 31;
    int nw = (blockDim.x + 31) >> 5;
    if (l == 0) { sa[w] = a; sb2[w] = b; }
    __syncthreads();
    if (w == 0) {
        a = (l < nw) ? sa[l] : 0.f;
        b = (l < nw) ? sb2[l] : 0.f;
        #pragma unroll
        for (int o = 4; o; o >>= 1) {
            a += __shfl_xor_sync(0xffffffffu, a, o);
            b += __shfl_xor_sync(0xffffffffu, b, o);
        }
        if (l == 0) { sa[0] = a; sb2[0] = b; }
    }
    __syncthreads();
    return make_float2(sa[0], sb2[0]);
}

__global__ void reset_k() {
    if (threadIdx.x < 8) g_maxabs[threadIdx.x] = 0u;
}

__global__ __launch_bounds__(256) void absmax_all(const float* wq, const float* wk,
                                                  const float* wv, const float* wo,
                                                  const float* su, const float* sv,
                                                  const float* wup, const float* wdn) {
    int seg = blockIdx.x >> 8, blk = blockIdx.x & 255;
    const float* p; int n;
    switch (seg) {
        case 0: p = wq;  n = D_ * D_;   break;
        case 1: p = wk;  n = D_ * D_;   break;
        case 2: p = wv;  n = D_ * D_;   break;
        case 3: p = wo;  n = D_ * D_;   break;
        case 4: p = su;  n = S_ * S_;   break;
        case 5: p = sv;  n = S_ * S_;   break;
        case 6: p = wup; n = HID_ * D_; break;
        default: p = wdn; n = HID_ * D_; break;
    }
    float m = 0.f;
    for (int i = blk * 256 + threadIdx.x; i < n; i += 256 * 256)
        m = fmaxf(m, fabsf(p[i]));
    #pragma unroll
    for (int o = 16; o; o >>= 1) m = fmaxf(m, __shfl_xor_sync(0xffffffffu, m, o));
    __shared__ float sm[8];
    if ((threadIdx.x & 31) == 0) sm[threadIdx.x >> 5] = m;
    __syncthreads();
    if (threadIdx.x < 8) {
        m = sm[threadIdx.x];
        #pragma unroll
        for (int o = 4; o; o >>= 1) m = fmaxf(m, __shfl_xor_sync(0xffu, m, o));
        if (threadIdx.x == 0) atomicMax(&g_maxabs[seg], __float_as_uint(m));
    }
}

// quantize + B-side split [hi|hi], with destination row offset
__global__ __launch_bounds__(256) void quant_split_k(const float* __restrict__ w,
                                                     __half* __restrict__ out,
                                                     int K, int slot, int total, int rowoff) {
    float scale = __uint_as_float(g_maxabs[slot]) / 31.0f + 1e-8f;
    int idx = blockIdx.x * blockDim.x + threadIdx.x;
    if (idx >= total) return;
    int n = idx / K, k = idx - n * K;
    float q = rintf(w[idx] / scale);
    q = fminf(fmaxf(q, -31.f), 31.f);
    float x = q * scale;
    __half h = __float2half(x);
    size_t base = (size_t)(n + rowoff) * (2 * K) + k;
    out[base] = h; out[base + K] = h;
}

// plain B-side split (pre-fused fp32 input)
__global__ __launch_bounds__(256) void split_b_k(const float* __restrict__ in,
                                                 __half* __restrict__ out,
                                                 int K, int total, int rowoff) {
    int idx = blockIdx.x * blockDim.x + threadIdx.x;
    if (idx >= total) return;
    int n = idx / K, k = idx - n * K;
    __half h = __float2half(in[idx]);
    size_t base = (size_t)(n + rowoff) * (2 * K) + k;
    out[base] = h; out[base + K] = h;
}

// fw[h*64+s][k] = sum_j q(su)[s][j] * q(w)[h*64+j][k]  (quantization fused in)
__global__ __launch_bounds__(256) void fuse_stalk_q(const float* __restrict__ su,
                                                    const float* __restrict__ w,
                                                    float* __restrict__ fw,
                                                    int slot_s, int slot_w) {
    __shared__ float Ws[64][128];
    __shared__ float Ss[64][64];
    float sc_s = __uint_as_float(g_maxabs[slot_s]) / 31.0f + 1e-8f;
    float sc_w = __uint_as_float(g_maxabs[slot_w]) / 31.0f + 1e-8f;
    int h = blockIdx.y;
    int k0 = blockIdx.x * 128;
    int tid = threadIdx.x;
    #pragma unroll
    for (int it = 0; it < 8; ++it) {
        int chunk = tid + it * 256;
        int r = chunk >> 5, c4 = (chunk & 31) * 4;
        float4 v = *(const float4*)(w + (size_t)(h * 64 + r) * D_ + k0 + c4);
        Ws[r][c4 + 0] = fminf(fmaxf(rintf(v.x / sc_w), -31.f), 31.f) * sc_w;
        Ws[r][c4 + 1] = fminf(fmaxf(rintf(v.y / sc_w), -31.f), 31.f) * sc_w;
        Ws[r][c4 + 2] = fminf(fmaxf(rintf(v.z / sc_w), -31.f), 31.f) * sc_w;
        Ws[r][c4 + 3] = fminf(fmaxf(rintf(v.w / sc_w), -31.f), 31.f) * sc_w;
    }
    #pragma unroll
    for (int it = 0; it < 4; ++it) {
        int chunk = tid + it * 256;
        int r = chunk >> 4, c4 = (chunk & 15) * 4;
        float4 v = *(const float4*)(su + (size_t)r * 64 + c4);
        Ss[r][c4 + 0] = fminf(fmaxf(rintf(v.x / sc_s), -31.f), 31.f) * sc_s;
        Ss[r][c4 + 1] = fminf(fmaxf(rintf(v.y / sc_s), -31.f), 31.f) * sc_s;
        Ss[r][c4 + 2] = fminf(fmaxf(rintf(v.z / sc_s), -31.f), 31.f) * sc_s;
        Ss[r][c4 + 3] = fminf(fmaxf(rintf(v.w / sc_s), -31.f), 31.f) * sc_s;
    }
    __syncthreads();
    #pragma unroll 4
    for (int it = 0; it < 32; ++it) {
        int oidx = tid + it * 256;
        int s = oidx >> 7, kk = oidx & 127;
        float acc = 0.f;
        #pragma unroll
        for (int j = 0; j < 64; ++j) acc += Ss[s][j] * Ws[j][kk];
        fw[(size_t)(h * 64 + s) * D_ + k0 + kk] = acc;
    }
}

// layernorm(D) + A-side split [hi|lo]
__global__ __launch_bounds__(256) void ln_split_k(const float* __restrict__ x,
                                                  const float* __restrict__ g,
                                                  const float* __restrict__ bb,
                                                  __half* __restrict__ out) {
    int row = blockIdx.x;
    const float* xr = x + (size_t)row * D_;
    int c = threadIdx.x * 4;
    float4 v = *(const float4*)(xr + c);
    float s = v.x + v.y + v.z + v.w;
    float sq = v.x * v.x + v.y * v.y + v.z * v.z + v.w * v.w;
    float2 r = block_reduce2(s, sq);
    float mu = r.x * (1.0f / D_);
    float var = r.y * (1.0f / D_) - mu * mu;
    float inv = rsqrtf(var + 1e-5f);
    float4 gg = *(const float4*)(g + c);
    float4 bv = *(const float4*)(bb + c);
    float o[4];
    o[0] = (v.x - mu) * inv * gg.x + bv.x;
    o[1] = (v.y - mu) * inv * gg.y + bv.y;
    o[2] = (v.z - mu) * inv * gg.z + bv.z;
    o[3] = (v.w - mu) * inv * gg.w + bv.w;
    size_t base = (size_t)row * 2048 + c;
    #pragma unroll
    for (int p2 = 0; p2 < 2; ++p2) {
        float a0 = o[p2 * 2], a1 = o[p2 * 2 + 1];
        __half h0 = __float2half(a0), h1 = __float2half(a1);
        __half l0 = __float2half(a0 - __half2float(h0));
        __half l1 = __float2half(a1 - __half2float(h1));
        *(__half2*)(out + base + p2 * 2)        = __halves2half2(h0, h1);
        *(__half2*)(out + base + 1024 + p2 * 2) = __halves2half2(l0, l1);
    }
}

// SO(2) rotate + layernorm(HID) + SiLU + A-side split [hi|lo]
__global__ __launch_bounds__(256) void rot_split_k(const float* __restrict__ hin,
                                                   const float* __restrict__ theta,
                                                   const float* __restrict__ g,
                                                   const float* __restrict__ bb,
                                                   __half* __restrict__ out) {
    int row = blockIdx.x;
    const float* hrow = hin + (size_t)row * HID_;
    int tid = threadIdx.x;
    float r0[6], r1[6];
    float s = 0.f, sq = 0.f;
    #pragma unroll
    for (int i = 0; i < 6; ++i) {
        int p = tid + i * 256;
        float2 ab = *(const float2*)(hrow + 2 * p);
        float sn, cs;
        sincosf(theta[p], &sn, &cs);
        r0[i] = cs * ab.x - sn * ab.y;
        r1[i] = sn * ab.x + cs * ab.y;
        s += r0[i] + r1[i];
        sq += r0[i] * r0[i] + r1[i] * r1[i];
    }
    float2 r = block_reduce2(s, sq);
    float mu = r.x * (1.0f / HID_);
    float var = r.y * (1.0f / HID_) - mu * mu;
    float inv = rsqrtf(var + 1e-5f);
    size_t base = (size_t)row * (2 * HID_);
    #pragma unroll
    for (int i = 0; i < 6; ++i) {
        int p = tid + i * 256;
        int e0 = 2 * p, e1 = 2 * p + 1;
        float y0 = (r0[i] - mu) * inv * g[e0] + bb[e0];
        float y1 = (r1[i] - mu) * inv * g[e1] + bb[e1];
        y0 = y0 / (1.0f + __expf(-y0));
        y1 = y1 / (1.0f + __expf(-y1));
        __half h0 = __float2half(y0), h1 = __float2half(y1);
        __half l0 = __float2half(y0 - __half2float(h0));
        __half l1 = __float2half(y1 - __half2float(h1));
        *(__half2*)(out + base + e0)        = __halves2half2(h0, h1);
        *(__half2*)(out + base + HID_ + e0) = __halves2half2(l0, l1);
    }
}

// ---------------- host launcher ----------------
extern "C" void kernel_launch(void* const* d_in, const int* in_sizes, int n_in,
                              void* d_out, int out_size) {
    const float* x   = (const float*)d_in[0];
    const float* wq  = (const float*)d_in[1];
    const float* wk  = (const float*)d_in[2];
    const float* wv  = (const float*)d_in[3];
    const float* wo  = (const float*)d_in[4];
    const float* su  = (const float*)d_in[5];
    const float* sv  = (const float*)d_in[6];
    const float* ps  = (const float*)d_in[7];
    const float* n1g = (const float*)d_in[8];
    const float* n1b = (const float*)d_in[9];
    const float* n2g = (const float*)d_in[10];
    const float* n2b = (const float*)d_in[11];
    const float* wup = (const float*)d_in[12];
    const float* wdn = (const float*)d_in[13];
    const float* th  = (const float*)d_in[14];
    const float* mng = (const float*)d_in[15];
    const float* mnb = (const float*)d_in[16];
    float* out = (float*)d_out;

    float *fwq, *fwk, *hb;
    __half *ex, *eh, *eqkv, *ewo, *eup, *edn;
    cudaGetSymbolAddress((void**)&fwq, g_fwq);
    cudaGetSymbolAddress((void**)&fwk, g_fwk);
    cudaGetSymbolAddress((void**)&hb, g_h);
    cudaGetSymbolAddress((void**)&ex, e_x);
    cudaGetSymbolAddress((void**)&eh, e_h);
    cudaGetSymbolAddress((void**)&eqkv, e_qkv);
    cudaGetSymbolAddress((void**)&ewo, e_wo);
    cudaGetSymbolAddress((void**)&eup, e_up);
    cudaGetSymbolAddress((void**)&edn, e_dn);

    static bool attr_set = false;
    if (!attr_set) {
        cudaFuncSetAttribute(mm_hmma, cudaFuncAttributeMaxDynamicSharedMemorySize, MMX_SMEM);
        cudaFuncSetAttribute(flash_k, cudaFuncAttributeMaxDynamicSharedMemorySize, FL_SMEM);
        attr_set = true;
    }

    const int nDD = D_ * D_;
    const int nUP = HID_ * D_;

    // weight prep
    reset_k<<<1, 32>>>();
    absmax_all<<<2048, 256>>>(wq, wk, wv, wo, su, sv, wup, wdn);
    fuse_stalk_q<<<dim3(D_ / 128, H_), 256>>>(su, wq, fwq, 4, 0);
    fuse_stalk_q<<<dim3(D_ / 128, H_), 256>>>(sv, wk, fwk, 5, 1);
    split_b_k<<<(nDD + 255) / 256, 256>>>(fwq, eqkv, D_, nDD, 0);
    split_b_k<<<(nDD + 255) / 256, 256>>>(fwk, eqkv, D_, nDD, 1024);
    quant_split_k<<<(nDD + 255) / 256, 256>>>(wv, eqkv, D_, 2, nDD, 2048);
    quant_split_k<<<(nDD + 255) / 256, 256>>>(wo, ewo, D_, 3, nDD, 0);
    quant_split_k<<<(nUP + 255) / 256, 256>>>(wup, eup, D_, 6, nUP, 0);
    quant_split_k<<<(nUP + 255) / 256, 256>>>(wdn, edn, HID_, 7, nUP, 0);

    // attention half
    ln_split_k<<<NTOK, 256>>>(x, n1g, n1b, ex);
    mm_hmma<<<dim3(24, 32), 256, MMX_SMEM>>>(ex, eqkv, nullptr, hb, NTOK, 3 * D_, 2 * D_);
    flash_k<<<dim3(8, 64), 256, FL_SMEM>>>(hb, ps, ex);
    mm_hmma<<<dim3(8, 32), 256, MMX_SMEM>>>(ex, ewo, x, out, NTOK, D_, 2 * D_);

    // MLP half
    ln_split_k<<<NTOK, 256>>>(out, n2g, n2b, ex);
    mm_hmma<<<dim3(24, 32), 256, MMX_SMEM>>>(ex, eup, nullptr, hb, NTOK, HID_, 2 * D_);
    rot_split_k<<<NTOK, 256>>>(hb, th, mng, mnb, eh);
    mm_hmma<<<dim3(8, 32), 256, MMX_SMEM>>>(eh, edn, out, out, NTOK, D_, 2 * HID_);
}

// round 11
// speedup vs baseline: 2.2372x; 1.5884x over previous
#include <cuda_runtime.h>
#include <cuda_fp16.h>
#include <math.h>
#include <stdint.h>

// ---------------- problem constants ----------------
#define B_ 4
#define T_ 1024
#define D_ 1024
#define H_ 16
#define S_ 64
#define HID_ 3072
#define NTOK (B_*T_)            // 4096

// ---------------- device scratch ----------------
__device__ float g_h[(size_t)NTOK*HID_];            // QKV output, then MLP hidden (fp32)
__device__ unsigned g_maxabs[8];

// fp16 buffers (no split)
__device__ __half e_x  [(size_t)NTOK*D_];          // activations
__device__ __half e_h  [(size_t)NTOK*HID_];        // mlp hidden
__device__ __half e_qkv[(size_t)(3*D_)*D_];        // fused QKV weights
__device__ __half e_wo [(size_t)D_*D_];
__device__ __half e_up [(size_t)HID_*D_];
__device__ __half e_dn [(size_t)D_*HID_];

// ---------------- PTX helpers ----------------
__device__ __forceinline__ uint32_t s2u(const void* p) {
    uint32_t a;
    asm("{ .reg .u64 t; cvta.to.shared.u64 t, %1; cvt.u32.u64 %0, t; }" : "=r"(a) : "l"(p));
    return a;
}
__device__ __forceinline__ void ldsm4(uint32_t* r, uint32_t a) {
    asm volatile("ldmatrix.sync.aligned.m8n8.x4.shared.b16 {%0,%1,%2,%3}, [%4];"
        : "=r"(r[0]), "=r"(r[1]), "=r"(r[2]), "=r"(r[3]) : "r"(a));
}
__device__ __forceinline__ void ldsm4t(uint32_t* r, uint32_t a) {
    asm volatile("ldmatrix.sync.aligned.m8n8.x4.trans.shared.b16 {%0,%1,%2,%3}, [%4];"
        : "=r"(r[0]), "=r"(r[1]), "=r"(r[2]), "=r"(r[3]) : "r"(a));
}
__device__ __forceinline__ void ldsm2(uint32_t* r, uint32_t a) {
    asm volatile("ldmatrix.sync.aligned.m8n8.x2.shared.b16 {%0,%1}, [%2];"
        : "=r"(r[0]), "=r"(r[1]) : "r"(a));
}
__device__ __forceinline__ void mma16816(float* c, const uint32_t* a, const uint32_t* b) {
    asm volatile("mma.sync.aligned.m16n8k16.row.col.f32.f16.f16.f32 "
        "{%0,%1,%2,%3}, {%4,%5,%6,%7}, {%8,%9}, {%0,%1,%2,%3};"
        : "+f"(c[0]), "+f"(c[1]), "+f"(c[2]), "+f"(c[3])
        : "r"(a[0]), "r"(a[1]), "r"(a[2]), "r"(a[3]), "r"(b[0]), "r"(b[1]));
}
__device__ __forceinline__ void cpasync16(uint32_t dst, const void* src) {
    asm volatile("cp.async.cg.shared.global [%0], [%1], 16;" :: "r"(dst), "l"(src));
}
__device__ __forceinline__ uint32_t packh(float lo, float hi) {
    uint32_t r;
    asm("cvt.rn.f16x2.f32 %0, %1, %2;" : "=r"(r) : "f"(hi), "f"(lo));
    return r;
}

// ---------------- fp16 HMMA GEMM: C[M,N] = A[M,K] @ B[N,K]^T (+Res) ----------------
// CTA tile 128x128, 8 warps (2x4), warp tile 64x32, K-chunk 64, double-buffered cp.async.
#define MMX_SMEM 65536
__global__ __launch_bounds__(256) void mm_hmma(const __half* __restrict__ Ag,
                                               const __half* __restrict__ Bg,
                                               const float* __restrict__ Res,
                                               float* __restrict__ C,
                                               int M, int N, int K) {
    extern __shared__ char sm_[];
    uint32_t sbase = s2u(sm_);
    int tid = threadIdx.x, lane = tid & 31, wid = tid >> 5;
    int wm = wid >> 2, wn = wid & 3;
    int m0 = blockIdx.y * 128, n0 = blockIdx.x * 128;
    const __half* Ap = Ag + (size_t)m0 * K;
    const __half* Bp = Bg + (size_t)n0 * K;
    int NC = K >> 6;

    float c[4][4][4];
    #pragma unroll
    for (int i = 0; i < 4; ++i)
        #pragma unroll
        for (int j = 0; j < 4; ++j)
            #pragma unroll
            for (int e = 0; e < 4; ++e) c[i][j][e] = 0.f;

    int crow = tid >> 3, cch = tid & 7;

    #define COPY_CHUNK(cidx, buf) do {                                             \
        uint32_t Ab_ = sbase + (buf) * 32768;                                      \
        uint32_t Bb_ = Ab_ + 16384;                                                \
        int kc_ = (cidx) << 6;                                                     \
        _Pragma("unroll")                                                          \
        for (int i_ = 0; i_ < 4; ++i_) {                                           \
            int row_ = crow + i_ * 32;                                             \
            uint32_t dst_ = Ab_ + row_ * 128 + (((cch) ^ (row_ & 7)) << 4);        \
            cpasync16(dst_, Ap + (size_t)row_ * K + kc_ + cch * 8);                \
        }                                                                          \
        _Pragma("unroll")                                                          \
        for (int i_ = 0; i_ < 4; ++i_) {                                           \
            int row_ = crow + i_ * 32;                                             \
            uint32_t dst_ = Bb_ + row_ * 128 + (((cch) ^ (row_ & 7)) << 4);        \
            cpasync16(dst_, Bp + (size_t)row_ * K + kc_ + cch * 8);                \
        }                                                                          \
        asm volatile("cp.async.commit_group;" ::: "memory");                       \
    } while (0)

    COPY_CHUNK(0, 0);
    for (int c0 = 0; c0 < NC; ++c0) {
        int buf = c0 & 1;
        if (c0 + 1 < NC) {
            COPY_CHUNK(c0 + 1, buf ^ 1);
            asm volatile("cp.async.wait_group 1;" ::: "memory");
        } else {
            asm volatile("cp.async.wait_group 0;" ::: "memory");
        }
        __syncthreads();
        uint32_t Ab = sbase + buf * 32768;
        uint32_t Bb = Ab + 16384;
        #pragma unroll
        for (int ks = 0; ks < 4; ++ks) {
            uint32_t a[4][4], b[4][2];
            #pragma unroll
            for (int i = 0; i < 4; ++i) {
                int row = wm * 64 + i * 16 + (lane & 15);
                int ch = ks * 2 + (lane >> 4);
                ldsm4(a[i], Ab + row * 128 + ((ch ^ (row & 7)) << 4));
            }
            #pragma unroll
            for (int j = 0; j < 4; ++j) {
                int row = wn * 32 + j * 8 + (lane & 7);
                int ch = ks * 2 + ((lane >> 3) & 1);
                ldsm2(b[j], Bb + row * 128 + ((ch ^ (row & 7)) << 4));
            }
            #pragma unroll
            for (int i = 0; i < 4; ++i)
                #pragma unroll
                for (int j = 0; j < 4; ++j)
                    mma16816(c[i][j], a[i], b[j]);
        }
        __syncthreads();
    }
    #undef COPY_CHUNK

    int g = lane >> 2, tg = lane & 3;
    #pragma unroll
    for (int i = 0; i < 4; ++i) {
        int r0 = m0 + wm * 64 + i * 16 + g;
        #pragma unroll
        for (int j = 0; j < 4; ++j) {
            int cc = n0 + wn * 32 + j * 8 + tg * 2;
            float* p0 = C + (size_t)r0 * N + cc;
            float* p1 = C + (size_t)(r0 + 8) * N + cc;
            if (Res) {
                float2 v0 = *(const float2*)(Res + (size_t)r0 * N + cc);
                float2 v1 = *(const float2*)(Res + (size_t)(r0 + 8) * N + cc);
                *(float2*)p0 = make_float2(c[i][j][0] + v0.x, c[i][j][1] + v0.y);
                *(float2*)p1 = make_float2(c[i][j][2] + v1.x, c[i][j][3] + v1.y);
            } else {
                *(float2*)p0 = make_float2(c[i][j][0], c[i][j][1]);
                *(float2*)p1 = make_float2(c[i][j][2], c[i][j][3]);
            }
        }
    }
}

// ---------------- fused flash attention (pure fp16 operands, fp32 accum) ----------------
// smem: Qs[128][72] Ks[64][72] Vh[64][72] fp16  (36864 B)
#define FL_SMEM 36864
__global__ __launch_bounds__(256, 2) void flash_k(const float* __restrict__ qkv,
                                                  const float* __restrict__ p_scale,
                                                  __half* __restrict__ exo) {
    extern __shared__ char sm_[];
    uint32_t sb = s2u(sm_);
    const uint32_t sQ = sb, sK = sb + 18432, sVh = sb + 27648;
    __half* Qs = (__half*)sm_;
    __half* Ks = (__half*)(sm_ + 18432);
    __half* Vh = (__half*)(sm_ + 27648);

    int tid = threadIdx.x, lane = tid & 31, wid = tid >> 5;
    int qt = 7 - (int)blockIdx.x;               // big tiles first
    int bh = blockIdx.y, b = bh >> 4, h = bh & 15;

    const float* Qg = qkv + ((size_t)(b * T_ + qt * 128)) * 3072 + h * 64;
    const float* Kg = qkv + (size_t)(b * T_) * 3072 + 1024 + h * 64;
    const float* Vg = qkv + (size_t)(b * T_) * 3072 + 2048 + h * 64;

    // load Q (128x64 fp32 -> fp16, pitch 72)
    #pragma unroll
    for (int i = 0; i < 8; ++i) {
        int idx = tid + i * 256;
        int r = idx >> 4, c4 = (idx & 15) * 4;
        float4 v = *(const float4*)(Qg + (size_t)r * 3072 + c4);
        Qs[r * 72 + c4 + 0] = __float2half(v.x);
        Qs[r * 72 + c4 + 1] = __float2half(v.y);
        Qs[r * 72 + c4 + 2] = __float2half(v.z);
        Qs[r * 72 + c4 + 3] = __float2half(v.w);
    }

    float m0 = -INFINITY, m1 = -INFINITY, l0 = 0.f, l1 = 0.f;
    float O[8][4];
    #pragma unroll
    for (int j = 0; j < 8; ++j)
        #pragma unroll
        for (int e = 0; e < 4; ++e) O[j][e] = 0.f;

    float ps = p_scale[0];
    int g = lane >> 2, tg = lane & 3;
    int wr0 = wid * 16;
    int row_g0 = qt * 128 + wr0 + g;
    int nch = (qt * 128 + 128) >> 6;

    uint32_t aq_base = sQ + (wr0 + (lane & 15)) * 144 + (lane >> 4) * 16;
    uint32_t bk_base = sK + (((lane >> 3) & 2) * 4 + (lane & 7)) * 144 + ((lane >> 3) & 1) * 16;
    uint32_t v_roff = ((lane & 7) + ((lane >> 3) & 1) * 8) * 144 + ((lane >> 4) & 1) * 16;

    for (int ch = 0; ch < nch; ++ch) {
        int u0 = ch << 6;
        __syncthreads();
        // load K,V chunk (64x64 fp32 each -> fp16)
        #pragma unroll
        for (int i = 0; i < 4; ++i) {
            int idx = tid + i * 256;
            int r = idx >> 4, c4 = (idx & 15) * 4;
            float4 kv = *(const float4*)(Kg + (size_t)(u0 + r) * 3072 + c4);
            float4 vv = *(const float4*)(Vg + (size_t)(u0 + r) * 3072 + c4);
            Ks[r * 72 + c4 + 0] = __float2half(kv.x);
            Ks[r * 72 + c4 + 1] = __float2half(kv.y);
            Ks[r * 72 + c4 + 2] = __float2half(kv.z);
            Ks[r * 72 + c4 + 3] = __float2half(kv.w);
            Vh[r * 72 + c4 + 0] = __float2half(vv.x);
            Vh[r * 72 + c4 + 1] = __float2half(vv.y);
            Vh[r * 72 + c4 + 2] = __float2half(vv.z);
            Vh[r * 72 + c4 + 3] = __float2half(vv.w);
        }
        __syncthreads();

        // S = Q @ K^T  (K-dim 64 = 4 ksteps)
        float c[8][4];
        #pragma unroll
        for (int j = 0; j < 8; ++j)
            #pragma unroll
            for (int e = 0; e < 4; ++e) c[j][e] = 0.f;
        #pragma unroll
        for (int ks = 0; ks < 4; ++ks) {
            uint32_t a[4];
            ldsm4(a, aq_base + ks * 32);
            #pragma unroll
            for (int jp = 0; jp < 4; ++jp) {
                uint32_t bb[4];
                ldsm4(bb, bk_base + jp * 16 * 144 + ks * 32);
                mma16816(c[jp * 2], a, bb);
                mma16816(c[jp * 2 + 1], a, bb + 2);
            }
        }

        // scale + p-adic bias + causal mask
        #pragma unroll
        for (int j = 0; j < 8; ++j) {
            int ub = u0 + j * 8 + tg * 2;
            #pragma unroll
            for (int e = 0; e < 4; ++e) {
                int row = row_g0 + (e >> 1) * 8;
                int u = ub + (e & 1);
                int d = row - u;
                if (d < 0) c[j][e] = -INFINITY;
                else {
                    float bias;
                    if (d == 0) bias = 1.f;
                    else {
                        int vp = __ffs(d) - 1;
                        vp = vp > 16 ? 16 : vp;
                        bias = (float)vp * (1.f / 16.f);
                    }
                    c[j][e] = c[j][e] * 0.125f + ps * bias;
                }
            }
        }

        // online softmax
        float mx0 = -INFINITY, mx1 = -INFINITY;
        #pragma unroll
        for (int j = 0; j < 8; ++j) {
            mx0 = fmaxf(mx0, fmaxf(c[j][0], c[j][1]));
            mx1 = fmaxf(mx1, fmaxf(c[j][2], c[j][3]));
        }
        mx0 = fmaxf(mx0, __shfl_xor_sync(0xffffffffu, mx0, 1));
        mx0 = fmaxf(mx0, __shfl_xor_sync(0xffffffffu, mx0, 2));
        mx1 = fmaxf(mx1, __shfl_xor_sync(0xffffffffu, mx1, 1));
        mx1 = fmaxf(mx1, __shfl_xor_sync(0xffffffffu, mx1, 2));
        float mn0 = fmaxf(m0, mx0), mn1 = fmaxf(m1, mx1);
        float al0 = __expf(m0 - mn0), al1 = __expf(m1 - mn1);
        float s0 = 0.f, s1 = 0.f;
        #pragma unroll
        for (int j = 0; j < 8; ++j) {
            c[j][0] = __expf(c[j][0] - mn0);
            c[j][1] = __expf(c[j][1] - mn0);
            c[j][2] = __expf(c[j][2] - mn1);
            c[j][3] = __expf(c[j][3] - mn1);
            s0 += c[j][0] + c[j][1];
            s1 += c[j][2] + c[j][3];
        }
        s0 += __shfl_xor_sync(0xffffffffu, s0, 1);
        s0 += __shfl_xor_sync(0xffffffffu, s0, 2);
        s1 += __shfl_xor_sync(0xffffffffu, s1, 1);
        s1 += __shfl_xor_sync(0xffffffffu, s1, 2);
        l0 = l0 * al0 + s0;
        l1 = l1 * al1 + s1;
        #pragma unroll
        for (int j = 0; j < 8; ++j) {
            O[j][0] *= al0; O[j][1] *= al0;
            O[j][2] *= al1; O[j][3] *= al1;
        }
        m0 = mn0; m1 = mn1;

        // O += P @ V  (P fp16 single term)
        #pragma unroll
        for (int ms = 0; ms < 4; ++ms) {
            uint32_t ah[4];
            ah[0] = packh(c[2 * ms][0], c[2 * ms][1]);
            ah[1] = packh(c[2 * ms][2], c[2 * ms][3]);
            ah[2] = packh(c[2 * ms + 1][0], c[2 * ms + 1][1]);
            ah[3] = packh(c[2 * ms + 1][2], c[2 * ms + 1][3]);
            uint32_t vaddr = v_roff + ms * 16 * 144;
            #pragma unroll
            for (int jp = 0; jp < 4; ++jp) {
                uint32_t vh[4];
                ldsm4t(vh, sVh + vaddr + jp * 32);
                mma16816(O[jp * 2],     ah, vh);
                mma16816(O[jp * 2 + 1], ah, vh + 2);
            }
        }
    }

    // epilogue: stage fp32 O in smem, then coalesced fp16 write
    __syncthreads();
    float* Of = (float*)sm_;        // [128][66]
    float i0 = 1.f / l0, i1 = 1.f / l1;
    #pragma unroll
    for (int j = 0; j < 8; ++j) {
        int cc = j * 8 + tg * 2;
        Of[(wr0 + g) * 66 + cc]     = O[j][0] * i0;
        Of[(wr0 + g) * 66 + cc + 1] = O[j][1] * i0;
        Of[(wr0 + g + 8) * 66 + cc]     = O[j][2] * i1;
        Of[(wr0 + g + 8) * 66 + cc + 1] = O[j][3] * i1;
    }
    __syncthreads();
    #pragma unroll
    for (int i = 0; i < 16; ++i) {
        int idx2 = tid + i * 256;              // 4096 half2 units
        int r = idx2 >> 5, c2 = (idx2 & 31) * 2;
        float v0 = Of[r * 66 + c2], v1 = Of[r * 66 + c2 + 1];
        int tok = b * T_ + qt * 128 + r;
        size_t base = (size_t)tok * 1024 + h * 64 + c2;
        *(__half2*)(exo + base) = __halves2half2(__float2half(v0), __float2half(v1));
    }
}

// ---------------- reductions / prep ----------------
__device__ __forceinline__ float2 block_reduce2(float a, float b) {
    #pragma unroll
    for (int o = 16; o; o >>= 1) {
        a += __shfl_xor_sync(0xffffffffu, a, o);
        b += __shfl_xor_sync(0xffffffffu, b, o);
    }
    __shared__ float sa[8], sb2[8];
    int w = threadIdx.x >> 5, l = threadIdx.x & 31;
    int nw = (blockDim.x + 31) >> 5;
    if (l == 0) { sa[w] = a; sb2[w] = b; }
    __syncthreads();
    if (w == 0) {
        a = (l < nw) ? sa[l] : 0.f;
        b = (l < nw) ? sb2[l] : 0.f;
        #pragma unroll
        for (int o = 4; o; o >>= 1) {
            a += __shfl_xor_sync(0xffffffffu, a, o);
            b += __shfl_xor_sync(0xffffffffu, b, o);
        }
        if (l == 0) { sa[0] = a; sb2[0] = b; }
    }
    __syncthreads();
    return make_float2(sa[0], sb2[0]);
}

__global__ void reset_k() {
    if (threadIdx.x < 8) g_maxabs[threadIdx.x] = 0u;
}

__global__ __launch_bounds__(256) void absmax_all(const float* wq, const float* wk,
                                                  const float* wv, const float* wo,
                                                  const float* su, const float* sv,
                                                  const float* wup, const float* wdn) {
    int seg = blockIdx.x >> 8, blk = blockIdx.x & 255;
    const float* p; int n;
    switch (seg) {
        case 0: p = wq;  n = D_ * D_;   break;
        case 1: p = wk;  n = D_ * D_;   break;
        case 2: p = wv;  n = D_ * D_;   break;
        case 3: p = wo;  n = D_ * D_;   break;
        case 4: p = su;  n = S_ * S_;   break;
        case 5: p = sv;  n = S_ * S_;   break;
        case 6: p = wup; n = HID_ * D_; break;
        default: p = wdn; n = HID_ * D_; break;
    }
    float m = 0.f;
    for (int i = blk * 256 + threadIdx.x; i < n; i += 256 * 256)
        m = fmaxf(m, fabsf(p[i]));
    #pragma unroll
    for (int o = 16; o; o >>= 1) m = fmaxf(m, __shfl_xor_sync(0xffffffffu, m, o));
    __shared__ float sm[8];
    if ((threadIdx.x & 31) == 0) sm[threadIdx.x >> 5] = m;
    __syncthreads();
    if (threadIdx.x < 8) {
        m = sm[threadIdx.x];
        #pragma unroll
        for (int o = 4; o; o >>= 1) m = fmaxf(m, __shfl_xor_sync(0xffu, m, o));
        if (threadIdx.x == 0) atomicMax(&g_maxabs[seg], __float_as_uint(m));
    }
}

// quantize -> fp16, with destination row offset
__global__ __launch_bounds__(256) void quant_half_k(const float* __restrict__ w,
                                                    __half* __restrict__ out,
                                                    int K, int slot, int total, int rowoff) {
    float scale = __uint_as_float(g_maxabs[slot]) / 31.0f + 1e-8f;
    int idx = blockIdx.x * blockDim.x + threadIdx.x;
    if (idx >= total) return;
    float q = rintf(w[idx] / scale);
    q = fminf(fmaxf(q, -31.f), 31.f);
    out[(size_t)rowoff * K + idx] = __float2half(q * scale);
}

// fw[h*64+s][k] = sum_j q(su)[s][j] * q(w)[h*64+j][k], output fp16 directly to eqkv
__global__ __launch_bounds__(256) void fuse_stalk_q(const float* __restrict__ su,
                                                    const float* __restrict__ w,
                                                    __half* __restrict__ out,
                                                    int slot_s, int slot_w, int rowoff) {
    __shared__ float Ws[64][64];
    __shared__ float Ss[64][64];
    float sc_s = __uint_as_float(g_maxabs[slot_s]) / 31.0f + 1e-8f;
    float sc_w = __uint_as_float(g_maxabs[slot_w]) / 31.0f + 1e-8f;
    int h = blockIdx.y;
    int k0 = blockIdx.x * 64;
    int tid = threadIdx.x;
    #pragma unroll
    for (int it = 0; it < 4; ++it) {
        int chunk = tid + it * 256;
        int r = chunk >> 4, c4 = (chunk & 15) * 4;
        float4 v = *(const float4*)(w + (size_t)(h * 64 + r) * D_ + k0 + c4);
        Ws[r][c4 + 0] = fminf(fmaxf(rintf(v.x / sc_w), -31.f), 31.f) * sc_w;
        Ws[r][c4 + 1] = fminf(fmaxf(rintf(v.y / sc_w), -31.f), 31.f) * sc_w;
        Ws[r][c4 + 2] = fminf(fmaxf(rintf(v.z / sc_w), -31.f), 31.f) * sc_w;
        Ws[r][c4 + 3] = fminf(fmaxf(rintf(v.w / sc_w), -31.f), 31.f) * sc_w;
    }
    #pragma unroll
    for (int it = 0; it < 4; ++it) {
        int chunk = tid + it * 256;
        int r = chunk >> 4, c4 = (chunk & 15) * 4;
        float4 v = *(const float4*)(su + (size_t)r * 64 + c4);
        Ss[r][c4 + 0] = fminf(fmaxf(rintf(v.x / sc_s), -31.f), 31.f) * sc_s;
        Ss[r][c4 + 1] = fminf(fmaxf(rintf(v.y / sc_s), -31.f), 31.f) * sc_s;
        Ss[r][c4 + 2] = fminf(fmaxf(rintf(v.z / sc_s), -31.f), 31.f) * sc_s;
        Ss[r][c4 + 3] = fminf(fmaxf(rintf(v.w / sc_s), -31.f), 31.f) * sc_s;
    }
    __syncthreads();
    #pragma unroll 4
    for (int it = 0; it < 16; ++it) {
        int oidx = tid + it * 256;
        int s = oidx >> 6, kk = oidx & 63;
        float acc = 0.f;
        #pragma unroll
        for (int j = 0; j < 64; ++j) acc += Ss[s][j] * Ws[j][kk];
        out[(size_t)(rowoff + h * 64 + s) * D_ + k0 + kk] = __float2half(acc);
    }
}

// layernorm(D) -> fp16
__global__ __launch_bounds__(256) void ln_half_k(const float* __restrict__ x,
                                                 const float* __restrict__ g,
                                                 const float* __restrict__ bb,
                                                 __half* __restrict__ out) {
    int row = blockIdx.x;
    const float* xr = x + (size_t)row * D_;
    int c = threadIdx.x * 4;
    float4 v = *(const float4*)(xr + c);
    float s = v.x + v.y + v.z + v.w;
    float sq = v.x * v.x + v.y * v.y + v.z * v.z + v.w * v.w;
    float2 r = block_reduce2(s, sq);
    float mu = r.x * (1.0f / D_);
    float var = r.y * (1.0f / D_) - mu * mu;
    float inv = rsqrtf(var + 1e-5f);
    float4 gg = *(const float4*)(g + c);
    float4 bv = *(const float4*)(bb + c);
    __half2 o0 = __halves2half2(__float2half((v.x - mu) * inv * gg.x + bv.x),
                                __float2half((v.y - mu) * inv * gg.y + bv.y));
    __half2 o1 = __halves2half2(__float2half((v.z - mu) * inv * gg.z + bv.z),
                                __float2half((v.w - mu) * inv * gg.w + bv.w));
    *(__half2*)(out + (size_t)row * D_ + c)     = o0;
    *(__half2*)(out + (size_t)row * D_ + c + 2) = o1;
}

// SO(2) rotate + layernorm(HID) + SiLU -> fp16
__global__ __launch_bounds__(256) void rot_half_k(const float* __restrict__ hin,
                                                  const float* __restrict__ theta,
                                                  const float* __restrict__ g,
                                                  const float* __restrict__ bb,
                                                  __half* __restrict__ out) {
    int row = blockIdx.x;
    const float* hrow = hin + (size_t)row * HID_;
    int tid = threadIdx.x;
    float r0[6], r1[6];
    float s = 0.f, sq = 0.f;
    #pragma unroll
    for (int i = 0; i < 6; ++i) {
        int p = tid + i * 256;
        float2 ab = *(const float2*)(hrow + 2 * p);
        float sn, cs;
        sincosf(theta[p], &sn, &cs);
        r0[i] = cs * ab.x - sn * ab.y;
        r1[i] = sn * ab.x + cs * ab.y;
        s += r0[i] + r1[i];
        sq += r0[i] * r0[i] + r1[i] * r1[i];
    }
    float2 r = block_reduce2(s, sq);
    float mu = r.x * (1.0f / HID_);
    float var = r.y * (1.0f / HID_) - mu * mu;
    float inv = rsqrtf(var + 1e-5f);
    size_t base = (size_t)row * HID_;
    #pragma unroll
    for (int i = 0; i < 6; ++i) {
        int p = tid + i * 256;
        int e0 = 2 * p, e1 = 2 * p + 1;
        float y0 = (r0[i] - mu) * inv * g[e0] + bb[e0];
        float y1 = (r1[i] - mu) * inv * g[e1] + bb[e1];
        y0 = y0 / (1.0f + __expf(-y0));
        y1 = y1 / (1.0f + __expf(-y1));
        *(__half2*)(out + base + e0) = __halves2half2(__float2half(y0), __float2half(y1));
    }
}

// ---------------- host launcher ----------------
extern "C" void kernel_launch(void* const* d_in, const int* in_sizes, int n_in,
                              void* d_out, int out_size) {
    const float* x   = (const float*)d_in[0];
    const float* wq  = (const float*)d_in[1];
    const float* wk  = (const float*)d_in[2];
    const float* wv  = (const float*)d_in[3];
    const float* wo  = (const float*)d_in[4];
    const float* su  = (const float*)d_in[5];
    const float* sv  = (const float*)d_in[6];
    const float* ps  = (const float*)d_in[7];
    const float* n1g = (const float*)d_in[8];
    const float* n1b = (const float*)d_in[9];
    const float* n2g = (const float*)d_in[10];
    const float* n2b = (const float*)d_in[11];
    const float* wup = (const float*)d_in[12];
    const float* wdn = (const float*)d_in[13];
    const float* th  = (const float*)d_in[14];
    const float* mng = (const float*)d_in[15];
    const float* mnb = (const float*)d_in[16];
    float* out = (float*)d_out;

    float* hb;
    __half *ex, *eh, *eqkv, *ewo, *eup, *edn;
    cudaGetSymbolAddress((void**)&hb, g_h);
    cudaGetSymbolAddress((void**)&ex, e_x);
    cudaGetSymbolAddress((void**)&eh, e_h);
    cudaGetSymbolAddress((void**)&eqkv, e_qkv);
    cudaGetSymbolAddress((void**)&ewo, e_wo);
    cudaGetSymbolAddress((void**)&eup, e_up);
    cudaGetSymbolAddress((void**)&edn, e_dn);

    static bool attr_set = false;
    if (!attr_set) {
        cudaFuncSetAttribute(mm_hmma, cudaFuncAttributeMaxDynamicSharedMemorySize, MMX_SMEM);
        cudaFuncSetAttribute(flash_k, cudaFuncAttributeMaxDynamicSharedMemorySize, FL_SMEM);
        attr_set = true;
    }

    const int nDD = D_ * D_;
    const int nUP = HID_ * D_;

    // weight prep
    reset_k<<<1, 32>>>();
    absmax_all<<<2048, 256>>>(wq, wk, wv, wo, su, sv, wup, wdn);
    fuse_stalk_q<<<dim3(D_ / 64, H_), 256>>>(su, wq, eqkv, 4, 0, 0);
    fuse_stalk_q<<<dim3(D_ / 64, H_), 256>>>(sv, wk, eqkv, 5, 1, 1024);
    quant_half_k<<<(nDD + 255) / 256, 256>>>(wv, eqkv, D_, 2, nDD, 2048);
    quant_half_k<<<(nDD + 255) / 256, 256>>>(wo, ewo, D_, 3, nDD, 0);
    quant_half_k<<<(nUP + 255) / 256, 256>>>(wup, eup, D_, 6, nUP, 0);
    quant_half_k<<<(nUP + 255) / 256, 256>>>(wdn, edn, HID_, 7, nUP, 0);

    // attention half
    ln_half_k<<<NTOK, 256>>>(x, n1g, n1b, ex);
    mm_hmma<<<dim3(24, 32), 256, MMX_SMEM>>>(ex, eqkv, nullptr, hb, NTOK, 3 * D_, D_);
    flash_k<<<dim3(8, 64), 256, FL_SMEM>>>(hb, ps, ex);
    mm_hmma<<<dim3(8, 32), 256, MMX_SMEM>>>(ex, ewo, x, out, NTOK, D_, D_);

    // MLP half
    ln_half_k<<<NTOK, 256>>>(out, n2g, n2b, ex);
    mm_hmma<<<dim3(24, 32), 256, MMX_SMEM>>>(ex, eup, nullptr, hb, NTOK, HID_, D_);
    rot_half_k<<<NTOK, 256>>>(hb, th, mng, mnb, eh);
    mm_hmma<<<dim3(8, 32), 256, MMX_SMEM>>>(eh, edn, out, out, NTOK, D_, HID_);
}

// round 13
// speedup vs baseline: 2.2407x; 1.0016x over previous
#include <cuda_runtime.h>
#include <cuda_fp16.h>
#include <math.h>
#include <stdint.h>

// ---------------- problem constants ----------------
#define B_ 4
#define T_ 1024
#define D_ 1024
#define H_ 16
#define S_ 64
#define HID_ 3072
#define NTOK (B_*T_)            // 4096

// ---------------- device scratch ----------------
__device__ float g_h[(size_t)NTOK*HID_];     // byte arena: fp16 QKV / fp16 mlp-hidden
__device__ unsigned g_maxabs[8];

// fp16 buffers
__device__ __half e_x  [(size_t)NTOK*D_];          // activations
__device__ __half e_h  [(size_t)NTOK*HID_];        // rot output (down-GEMM A)
__device__ __half e_qkv[(size_t)(3*D_)*D_];        // fused QKV weights
__device__ __half e_wo [(size_t)D_*D_];
__device__ __half e_up [(size_t)HID_*D_];
__device__ __half e_dn [(size_t)D_*HID_];

// ---------------- PTX helpers ----------------
__device__ __forceinline__ uint32_t s2u(const void* p) {
    uint32_t a;
    asm("{ .reg .u64 t; cvta.to.shared.u64 t, %1; cvt.u32.u64 %0, t; }" : "=r"(a) : "l"(p));
    return a;
}
__device__ __forceinline__ void ldsm4(uint32_t* r, uint32_t a) {
    asm volatile("ldmatrix.sync.aligned.m8n8.x4.shared.b16 {%0,%1,%2,%3}, [%4];"
        : "=r"(r[0]), "=r"(r[1]), "=r"(r[2]), "=r"(r[3]) : "r"(a));
}
__device__ __forceinline__ void ldsm4t(uint32_t* r, uint32_t a) {
    asm volatile("ldmatrix.sync.aligned.m8n8.x4.trans.shared.b16 {%0,%1,%2,%3}, [%4];"
        : "=r"(r[0]), "=r"(r[1]), "=r"(r[2]), "=r"(r[3]) : "r"(a));
}
__device__ __forceinline__ void mma16816(float* c, const uint32_t* a, const uint32_t* b) {
    asm volatile("mma.sync.aligned.m16n8k16.row.col.f32.f16.f16.f32 "
        "{%0,%1,%2,%3}, {%4,%5,%6,%7}, {%8,%9}, {%0,%1,%2,%3};"
        : "+f"(c[0]), "+f"(c[1]), "+f"(c[2]), "+f"(c[3])
        : "r"(a[0]), "r"(a[1]), "r"(a[2]), "r"(a[3]), "r"(b[0]), "r"(b[1]));
}
__device__ __forceinline__ void cpasync16(uint32_t dst, const void* src) {
    asm volatile("cp.async.cg.shared.global [%0], [%1], 16;" :: "r"(dst), "l"(src));
}
__device__ __forceinline__ uint32_t packh(float lo, float hi) {
    uint32_t r;
    asm("cvt.rn.f16x2.f32 %0, %1, %2;" : "=r"(r) : "f"(hi), "f"(lo));
    return r;
}

// ---------------- fp16 HMMA GEMM: C/Ch[M,N] = A[M,K] @ B[N,K]^T (+Res) ----------------
// CTA 128x128, 8 warps (2x4), warp tile 64x32, K-chunk 64, double-buffered cp.async.
// If Ch != null -> fp16 output (no residual). Else fp32 output (+Res).
#define MMX_SMEM 65536
__global__ __launch_bounds__(256) void mm_hmma(const __half* __restrict__ Ag,
                                               const __half* __restrict__ Bg,
                                               const float* __restrict__ Res,
                                               float* __restrict__ C,
                                               __half* __restrict__ Ch,
                                               int M, int N, int K) {
    extern __shared__ char sm_[];
    uint32_t sbase = s2u(sm_);
    int tid = threadIdx.x, lane = tid & 31, wid = tid >> 5;
    int wm = wid >> 2, wn = wid & 3;
    int m0 = blockIdx.y * 128, n0 = blockIdx.x * 128;
    const __half* Ap = Ag + (size_t)m0 * K;
    const __half* Bp = Bg + (size_t)n0 * K;
    int NC = K >> 6;

    float c[4][4][4];
    #pragma unroll
    for (int i = 0; i < 4; ++i)
        #pragma unroll
        for (int j = 0; j < 4; ++j)
            #pragma unroll
            for (int e = 0; e < 4; ++e) c[i][j][e] = 0.f;

    int crow = tid >> 3, cch = tid & 7;

    #define COPY_CHUNK(cidx, buf) do {                                             \
        uint32_t Ab_ = sbase + (buf) * 32768;                                      \
        uint32_t Bb_ = Ab_ + 16384;                                                \
        int kc_ = (cidx) << 6;                                                     \
        _Pragma("unroll")                                                          \
        for (int i_ = 0; i_ < 4; ++i_) {                                           \
            int row_ = crow + i_ * 32;                                             \
            uint32_t dst_ = Ab_ + row_ * 128 + (((cch) ^ (row_ & 7)) << 4);        \
            cpasync16(dst_, Ap + (size_t)row_ * K + kc_ + cch * 8);                \
        }                                                                          \
        _Pragma("unroll")                                                          \
        for (int i_ = 0; i_ < 4; ++i_) {                                           \
            int row_ = crow + i_ * 32;                                             \
            uint32_t dst_ = Bb_ + row_ * 128 + (((cch) ^ (row_ & 7)) << 4);        \
            cpasync16(dst_, Bp + (size_t)row_ * K + kc_ + cch * 8);                \
        }                                                                          \
        asm volatile("cp.async.commit_group;" ::: "memory");                       \
    } while (0)

    COPY_CHUNK(0, 0);
    for (int c0 = 0; c0 < NC; ++c0) {
        int buf = c0 & 1;
        if (c0 + 1 < NC) {
            COPY_CHUNK(c0 + 1, buf ^ 1);
            asm volatile("cp.async.wait_group 1;" ::: "memory");
        } else {
            asm volatile("cp.async.wait_group 0;" ::: "memory");
        }
        __syncthreads();
        uint32_t Ab = sbase + buf * 32768;
        uint32_t Bb = Ab + 16384;
        #pragma unroll
        for (int ks = 0; ks < 4; ++ks) {
            uint32_t a[4][4], b[2][4];
            #pragma unroll
            for (int i = 0; i < 4; ++i) {
                int row = wm * 64 + i * 16 + (lane & 15);
                int ch = ks * 2 + (lane >> 4);
                ldsm4(a[i], Ab + row * 128 + ((ch ^ (row & 7)) << 4));
            }
            // B via ldsm4 pairs (R8-validated mapping): frag {b[q][0],b[q][1]} = n-lo 8,
            // {b[q][2],b[q][3]} = n-hi 8 of the 16-row group q.
            #pragma unroll
            for (int jq = 0; jq < 2; ++jq) {
                int row = wn * 32 + jq * 16 + ((lane >> 4) & 1) * 8 + (lane & 7);
                int ch = ks * 2 + ((lane >> 3) & 1);
                ldsm4(b[jq], Bb + row * 128 + ((ch ^ (row & 7)) << 4));
            }
            #pragma unroll
            for (int i = 0; i < 4; ++i)
                #pragma unroll
                for (int j = 0; j < 4; ++j)
                    mma16816(c[i][j], a[i], &b[j >> 1][(j & 1) * 2]);
        }
        __syncthreads();
    }
    #undef COPY_CHUNK

    int g = lane >> 2, tg = lane & 3;
    if (Ch) {
        #pragma unroll
        for (int i = 0; i < 4; ++i) {
            int r0 = m0 + wm * 64 + i * 16 + g;
            #pragma unroll
            for (int j = 0; j < 4; ++j) {
                int cc = n0 + wn * 32 + j * 8 + tg * 2;
                *(__half2*)(Ch + (size_t)r0 * N + cc) =
                    __halves2half2(__float2half(c[i][j][0]), __float2half(c[i][j][1]));
                *(__half2*)(Ch + (size_t)(r0 + 8) * N + cc) =
                    __halves2half2(__float2half(c[i][j][2]), __float2half(c[i][j][3]));
            }
        }
    } else {
        #pragma unroll
        for (int i = 0; i < 4; ++i) {
            int r0 = m0 + wm * 64 + i * 16 + g;
            #pragma unroll
            for (int j = 0; j < 4; ++j) {
                int cc = n0 + wn * 32 + j * 8 + tg * 2;
                float* p0 = C + (size_t)r0 * N + cc;
                float* p1 = C + (size_t)(r0 + 8) * N + cc;
                if (Res) {
                    float2 v0 = *(const float2*)(Res + (size_t)r0 * N + cc);
                    float2 v1 = *(const float2*)(Res + (size_t)(r0 + 8) * N + cc);
                    *(float2*)p0 = make_float2(c[i][j][0] + v0.x, c[i][j][1] + v0.y);
                    *(float2*)p1 = make_float2(c[i][j][2] + v1.x, c[i][j][3] + v1.y);
                } else {
                    *(float2*)p0 = make_float2(c[i][j][0], c[i][j][1]);
                    *(float2*)p1 = make_float2(c[i][j][2], c[i][j][3]);
                }
            }
        }
    }
}

// ---------------- fused flash attention (fp16 QKV input via cp.async) ----------------
// smem: Qs[128][72] Ks[64][72] Vh[64][72] fp16  (36864 B)
#define FL_SMEM 36864
__global__ __launch_bounds__(256, 2) void flash_k(const __half* __restrict__ qkv,
                                                  const float* __restrict__ p_scale,
                                                  __half* __restrict__ exo) {
    extern __shared__ char sm_[];
    uint32_t sb = s2u(sm_);
    const uint32_t sQ = sb, sK = sb + 18432, sVh = sb + 27648;

    int tid = threadIdx.x, lane = tid & 31, wid = tid >> 5;
    int qt = 7 - (int)blockIdx.x;               // big tiles first
    int bh = blockIdx.y, b = bh >> 4, h = bh & 15;

    const __half* Qg = qkv + ((size_t)(b * T_ + qt * 128)) * 3072 + h * 64;
    const __half* Kg = qkv + (size_t)(b * T_) * 3072 + 1024 + h * 64;
    const __half* Vg = qkv + (size_t)(b * T_) * 3072 + 2048 + h * 64;

    // Q tile: 128 rows x 128B = 1024 16B-chunks, cp.async
    #pragma unroll
    for (int i = 0; i < 4; ++i) {
        int idx = tid + i * 256;
        int r = idx >> 3, cc = idx & 7;
        cpasync16(sQ + r * 144 + cc * 16, Qg + (size_t)r * 3072 + cc * 8);
    }
    asm volatile("cp.async.commit_group;" ::: "memory");

    float m0 = -INFINITY, m1 = -INFINITY, l0 = 0.f, l1 = 0.f;
    float O[8][4];
    #pragma unroll
    for (int j = 0; j < 8; ++j)
        #pragma unroll
        for (int e = 0; e < 4; ++e) O[j][e] = 0.f;

    float ps = p_scale[0];
    int g = lane >> 2, tg = lane & 3;
    int wr0 = wid * 16;
    int row_g0 = qt * 128 + wr0 + g;
    int nch = (qt * 128 + 128) >> 6;

    uint32_t aq_base = sQ + (wr0 + (lane & 15)) * 144 + (lane >> 4) * 16;
    uint32_t bk_base = sK + (((lane >> 3) & 2) * 4 + (lane & 7)) * 144 + ((lane >> 3) & 1) * 16;
    uint32_t v_roff = ((lane & 7) + ((lane >> 3) & 1) * 8) * 144 + ((lane >> 4) & 1) * 16;

    for (int ch = 0; ch < nch; ++ch) {
        int u0 = ch << 6;
        __syncthreads();
        // K,V chunk: 64 rows x 8 chunks each = 512+512 chunks, cp.async
        #pragma unroll
        for (int i = 0; i < 2; ++i) {
            int idx = tid + i * 256;
            int r = idx >> 3, cc = idx & 7;
            cpasync16(sK + r * 144 + cc * 16, Kg + (size_t)(u0 + r) * 3072 + cc * 8);
            cpasync16(sVh + r * 144 + cc * 16, Vg + (size_t)(u0 + r) * 3072 + cc * 8);
        }
        asm volatile("cp.async.commit_group;" ::: "memory");
        asm volatile("cp.async.wait_group 0;" ::: "memory");
        __syncthreads();

        // S = Q @ K^T  (K-dim 64 = 4 ksteps)
        float c[8][4];
        #pragma unroll
        for (int j = 0; j < 8; ++j)
            #pragma unroll
            for (int e = 0; e < 4; ++e) c[j][e] = 0.f;
        #pragma unroll
        for (int ks = 0; ks < 4; ++ks) {
            uint32_t a[4];
            ldsm4(a, aq_base + ks * 32);
            #pragma unroll
            for (int jp = 0; jp < 4; ++jp) {
                uint32_t bb[4];
                ldsm4(bb, bk_base + jp * 16 * 144 + ks * 32);
                mma16816(c[jp * 2], a, bb);
                mma16816(c[jp * 2 + 1], a, bb + 2);
            }
        }

        // scale + p-adic bias + causal mask
        #pragma unroll
        for (int j = 0; j < 8; ++j) {
            int ub = u0 + j * 8 + tg * 2;
            #pragma unroll
            for (int e = 0; e < 4; ++e) {
                int row = row_g0 + (e >> 1) * 8;
                int u = ub + (e & 1);
                int d = row - u;
                if (d < 0) c[j][e] = -INFINITY;
                else {
                    float bias;
                    if (d == 0) bias = 1.f;
                    else {
                        int vp = __ffs(d) - 1;
                        vp = vp > 16 ? 16 : vp;
                        bias = (float)vp * (1.f / 16.f);
                    }
                    c[j][e] = c[j][e] * 0.125f + ps * bias;
                }
            }
        }

        // online softmax
        float mx0 = -INFINITY, mx1 = -INFINITY;
        #pragma unroll
        for (int j = 0; j < 8; ++j) {
            mx0 = fmaxf(mx0, fmaxf(c[j][0], c[j][1]));
            mx1 = fmaxf(mx1, fmaxf(c[j][2], c[j][3]));
        }
        mx0 = fmaxf(mx0, __shfl_xor_sync(0xffffffffu, mx0, 1));
        mx0 = fmaxf(mx0, __shfl_xor_sync(0xffffffffu, mx0, 2));
        mx1 = fmaxf(mx1, __shfl_xor_sync(0xffffffffu, mx1, 1));
        mx1 = fmaxf(mx1, __shfl_xor_sync(0xffffffffu, mx1, 2));
        float mn0 = fmaxf(m0, mx0), mn1 = fmaxf(m1, mx1);
        float al0 = __expf(m0 - mn0), al1 = __expf(m1 - mn1);
        float s0 = 0.f, s1 = 0.f;
        #pragma unroll
        for (int j = 0; j < 8; ++j) {
            c[j][0] = __expf(c[j][0] - mn0);
            c[j][1] = __expf(c[j][1] - mn0);
            c[j][2] = __expf(c[j][2] - mn1);
            c[j][3] = __expf(c[j][3] - mn1);
            s0 += c[j][0] + c[j][1];
            s1 += c[j][2] + c[j][3];
        }
        s0 += __shfl_xor_sync(0xffffffffu, s0, 1);
        s0 += __shfl_xor_sync(0xffffffffu, s0, 2);
        s1 += __shfl_xor_sync(0xffffffffu, s1, 1);
        s1 += __shfl_xor_sync(0xffffffffu, s1, 2);
        l0 = l0 * al0 + s0;
        l1 = l1 * al1 + s1;
        #pragma unroll
        for (int j = 0; j < 8; ++j) {
            O[j][0] *= al0; O[j][1] *= al0;
            O[j][2] *= al1; O[j][3] *= al1;
        }
        m0 = mn0; m1 = mn1;

        // O += P @ V
        #pragma unroll
        for (int ms = 0; ms < 4; ++ms) {
            uint32_t ah[4];
            ah[0] = packh(c[2 * ms][0], c[2 * ms][1]);
            ah[1] = packh(c[2 * ms][2], c[2 * ms][3]);
            ah[2] = packh(c[2 * ms + 1][0], c[2 * ms + 1][1]);
            ah[3] = packh(c[2 * ms + 1][2], c[2 * ms + 1][3]);
            uint32_t vaddr = v_roff + ms * 16 * 144;
            #pragma unroll
            for (int jp = 0; jp < 4; ++jp) {
                uint32_t vh[4];
                ldsm4t(vh, sVh + vaddr + jp * 32);
                mma16816(O[jp * 2],     ah, vh);
                mma16816(O[jp * 2 + 1], ah, vh + 2);
            }
        }
    }

    // epilogue: stage fp32 O in smem, then coalesced fp16 write
    __syncthreads();
    float* Of = (float*)sm_;        // [128][66]
    float i0 = 1.f / l0, i1 = 1.f / l1;
    #pragma unroll
    for (int j = 0; j < 8; ++j) {
        int cc = j * 8 + tg * 2;
        Of[(wr0 + g) * 66 + cc]     = O[j][0] * i0;
        Of[(wr0 + g) * 66 + cc + 1] = O[j][1] * i0;
        Of[(wr0 + g + 8) * 66 + cc]     = O[j][2] * i1;
        Of[(wr0 + g + 8) * 66 + cc + 1] = O[j][3] * i1;
    }
    __syncthreads();
    #pragma unroll
    for (int i = 0; i < 16; ++i) {
        int idx2 = tid + i * 256;              // 4096 half2 units
        int r = idx2 >> 5, c2 = (idx2 & 31) * 2;
        float v0 = Of[r * 66 + c2], v1 = Of[r * 66 + c2 + 1];
        int tok = b * T_ + qt * 128 + r;
        size_t base = (size_t)tok * 1024 + h * 64 + c2;
        *(__half2*)(exo + base) = __halves2half2(__float2half(v0), __float2half(v1));
    }
}

// ---------------- reductions / prep ----------------
__device__ __forceinline__ float2 block_reduce2(float a, float b) {
    #pragma unroll
    for (int o = 16; o; o >>= 1) {
        a += __shfl_xor_sync(0xffffffffu, a, o);
        b += __shfl_xor_sync(0xffffffffu, b, o);
    }
    __shared__ float sa[8], sb2[8];
    int w = threadIdx.x >> 5, l = threadIdx.x & 31;
    int nw = (blockDim.x + 31) >> 5;
    if (l == 0) { sa[w] = a; sb2[w] = b; }
    __syncthreads();
    if (w == 0) {
        a = (l < nw) ? sa[l] : 0.f;
        b = (l < nw) ? sb2[l] : 0.f;
        #pragma unroll
        for (int o = 4; o; o >>= 1) {
            a += __shfl_xor_sync(0xffffffffu, a, o);
            b += __shfl_xor_sync(0xffffffffu, b, o);
        }
        if (l == 0) { sa[0] = a; sb2[0] = b; }
    }
    __syncthreads();
    return make_float2(sa[0], sb2[0]);
}

__global__ void reset_k() {
    if (threadIdx.x < 8) g_maxabs[threadIdx.x] = 0u;
}

__global__ __launch_bounds__(256) void absmax_all(const float* wq, const float* wk,
                                                  const float* wv, const float* wo,
                                                  const float* su, const float* sv,
                                                  const float* wup, const float* wdn) {
    int seg = blockIdx.x >> 8, blk = blockIdx.x & 255;
    const float* p; int n;
    switch (seg) {
        case 0: p = wq;  n = D_ * D_;   break;
        case 1: p = wk;  n = D_ * D_;   break;
        case 2: p = wv;  n = D_ * D_;   break;
        case 3: p = wo;  n = D_ * D_;   break;
        case 4: p = su;  n = S_ * S_;   break;
        case 5: p = sv;  n = S_ * S_;   break;
        case 6: p = wup; n = HID_ * D_; break;
        default: p = wdn; n = HID_ * D_; break;
    }
    float m = 0.f;
    for (int i = blk * 256 + threadIdx.x; i < n; i += 256 * 256)
        m = fmaxf(m, fabsf(p[i]));
    #pragma unroll
    for (int o = 16; o; o >>= 1) m = fmaxf(m, __shfl_xor_sync(0xffffffffu, m, o));
    __shared__ float sm[8];
    if ((threadIdx.x & 31) == 0) sm[threadIdx.x >> 5] = m;
    __syncthreads();
    if (threadIdx.x < 8) {
        m = sm[threadIdx.x];
        #pragma unroll
        for (int o = 4; o; o >>= 1) m = fmaxf(m, __shfl_xor_sync(0xffu, m, o));
        if (threadIdx.x == 0) atomicMax(&g_maxabs[seg], __float_as_uint(m));
    }
}

// quantize -> fp16, with destination row offset
__global__ __launch_bounds__(256) void quant_half_k(const float* __restrict__ w,
                                                    __half* __restrict__ out,
                                                    int K, int slot, int total, int rowoff) {
    float scale = __uint_as_float(g_maxabs[slot]) / 31.0f + 1e-8f;
    int idx = blockIdx.x * blockDim.x + threadIdx.x;
    if (idx >= total) return;
    float q = rintf(w[idx] / scale);
    q = fminf(fmaxf(q, -31.f), 31.f);
    out[(size_t)rowoff * K + idx] = __float2half(q * scale);
}

// fw[h*64+s][k] = sum_j q(su)[s][j] * q(w)[h*64+j][k], output fp16 directly to eqkv
__global__ __launch_bounds__(256) void fuse_stalk_q(const float* __restrict__ su,
                                                    const float* __restrict__ w,
                                                    __half* __restrict__ out,
                                                    int slot_s, int slot_w, int rowoff) {
    __shared__ float Ws[64][64];
    __shared__ float Ss[64][64];
    float sc_s = __uint_as_float(g_maxabs[slot_s]) / 31.0f + 1e-8f;
    float sc_w = __uint_as_float(g_maxabs[slot_w]) / 31.0f + 1e-8f;
    int h = blockIdx.y;
    int k0 = blockIdx.x * 64;
    int tid = threadIdx.x;
    #pragma unroll
    for (int it = 0; it < 4; ++it) {
        int chunk = tid + it * 256;
        int r = chunk >> 4, c4 = (chunk & 15) * 4;
        float4 v = *(const float4*)(w + (size_t)(h * 64 + r) * D_ + k0 + c4);
        Ws[r][c4 + 0] = fminf(fmaxf(rintf(v.x / sc_w), -31.f), 31.f) * sc_w;
        Ws[r][c4 + 1] = fminf(fmaxf(rintf(v.y / sc_w), -31.f), 31.f) * sc_w;
        Ws[r][c4 + 2] = fminf(fmaxf(rintf(v.z / sc_w), -31.f), 31.f) * sc_w;
        Ws[r][c4 + 3] = fminf(fmaxf(rintf(v.w / sc_w), -31.f), 31.f) * sc_w;
    }
    #pragma unroll
    for (int it = 0; it < 4; ++it) {
        int chunk = tid + it * 256;
        int r = chunk >> 4, c4 = (chunk & 15) * 4;
        float4 v = *(const float4*)(su + (size_t)r * 64 + c4);
        Ss[r][c4 + 0] = fminf(fmaxf(rintf(v.x / sc_s), -31.f), 31.f) * sc_s;
        Ss[r][c4 + 1] = fminf(fmaxf(rintf(v.y / sc_s), -31.f), 31.f) * sc_s;
        Ss[r][c4 + 2] = fminf(fmaxf(rintf(v.z / sc_s), -31.f), 31.f) * sc_s;
        Ss[r][c4 + 3] = fminf(fmaxf(rintf(v.w / sc_s), -31.f), 31.f) * sc_s;
    }
    __syncthreads();
    #pragma unroll 4
    for (int it = 0; it < 16; ++it) {
        int oidx = tid + it * 256;
        int s = oidx >> 6, kk = oidx & 63;
        float acc = 0.f;
        #pragma unroll
        for (int j = 0; j < 64; ++j) acc += Ss[s][j] * Ws[j][kk];
        out[(size_t)(rowoff + h * 64 + s) * D_ + k0 + kk] = __float2half(acc);
    }
}

// layernorm(D) -> fp16
__global__ __launch_bounds__(256) void ln_half_k(const float* __restrict__ x,
                                                 const float* __restrict__ g,
                                                 const float* __restrict__ bb,
                                                 __half* __restrict__ out) {
    int row = blockIdx.x;
    const float* xr = x + (size_t)row * D_;
    int c = threadIdx.x * 4;
    float4 v = *(const float4*)(xr + c);
    float s = v.x + v.y + v.z + v.w;
    float sq = v.x * v.x + v.y * v.y + v.z * v.z + v.w * v.w;
    float2 r = block_reduce2(s, sq);
    float mu = r.x * (1.0f / D_);
    float var = r.y * (1.0f / D_) - mu * mu;
    float inv = rsqrtf(var + 1e-5f);
    float4 gg = *(const float4*)(g + c);
    float4 bv = *(const float4*)(bb + c);
    __half2 o0 = __halves2half2(__float2half((v.x - mu) * inv * gg.x + bv.x),
                                __float2half((v.y - mu) * inv * gg.y + bv.y));
    __half2 o1 = __halves2half2(__float2half((v.z - mu) * inv * gg.z + bv.z),
                                __float2half((v.w - mu) * inv * gg.w + bv.w));
    *(__half2*)(out + (size_t)row * D_ + c)     = o0;
    *(__half2*)(out + (size_t)row * D_ + c + 2) = o1;
}

// SO(2) rotate + layernorm(HID) + SiLU -> fp16 (fp16 input)
__global__ __launch_bounds__(256) void rot_half_k(const __half* __restrict__ hin,
                                                  const float* __restrict__ theta,
                                                  const float* __restrict__ g,
                                                  const float* __restrict__ bb,
                                                  __half* __restrict__ out) {
    int row = blockIdx.x;
    const __half* hrow = hin + (size_t)row * HID_;
    int tid = threadIdx.x;
    float r0[6], r1[6];
    float s = 0.f, sq = 0.f;
    #pragma unroll
    for (int i = 0; i < 6; ++i) {
        int p = tid + i * 256;
        __half2 ab2 = *(const __half2*)(hrow + 2 * p);
        float ax = __half2float(__low2half(ab2));
        float ay = __half2float(__high2half(ab2));
        float sn, cs;
        sincosf(theta[p], &sn, &cs);
        r0[i] = cs * ax - sn * ay;
        r1[i] = sn * ax + cs * ay;
        s += r0[i] + r1[i];
        sq += r0[i] * r0[i] + r1[i] * r1[i];
    }
    float2 r = block_reduce2(s, sq);
    float mu = r.x * (1.0f / HID_);
    float var = r.y * (1.0f / HID_) - mu * mu;
    float inv = rsqrtf(var + 1e-5f);
    size_t base = (size_t)row * HID_;
    #pragma unroll
    for (int i = 0; i < 6; ++i) {
        int p = tid + i * 256;
        int e0 = 2 * p, e1 = 2 * p + 1;
        float y0 = (r0[i] - mu) * inv * g[e0] + bb[e0];
        float y1 = (r1[i] - mu) * inv * g[e1] + bb[e1];
        y0 = y0 / (1.0f + __expf(-y0));
        y1 = y1 / (1.0f + __expf(-y1));
        *(__half2*)(out + base + e0) = __halves2half2(__float2half(y0), __float2half(y1));
    }
}

// ---------------- host launcher ----------------
extern "C" void kernel_launch(void* const* d_in, const int* in_sizes, int n_in,
                              void* d_out, int out_size) {
    const float* x   = (const float*)d_in[0];
    const float* wq  = (const float*)d_in[1];
    const float* wk  = (const float*)d_in[2];
    const float* wv  = (const float*)d_in[3];
    const float* wo  = (const float*)d_in[4];
    const float* su  = (const float*)d_in[5];
    const float* sv  = (const float*)d_in[6];
    const float* ps  = (const float*)d_in[7];
    const float* n1g = (const float*)d_in[8];
    const float* n1b = (const float*)d_in[9];
    const float* n2g = (const float*)d_in[10];
    const float* n2b = (const float*)d_in[11];
    const float* wup = (const float*)d_in[12];
    const float* wdn = (const float*)d_in[13];
    const float* th  = (const float*)d_in[14];
    const float* mng = (const float*)d_in[15];
    const float* mnb = (const float*)d_in[16];
    float* out = (float*)d_out;

    float* hb;
    __half *ex, *eh, *eqkv, *ewo, *eup, *edn;
    cudaGetSymbolAddress((void**)&hb, g_h);
    cudaGetSymbolAddress((void**)&ex, e_x);
    cudaGetSymbolAddress((void**)&eh, e_h);
    cudaGetSymbolAddress((void**)&eqkv, e_qkv);
    cudaGetSymbolAddress((void**)&ewo, e_wo);
    cudaGetSymbolAddress((void**)&eup, e_up);
    cudaGetSymbolAddress((void**)&edn, e_dn);
    __half* hbh = (__half*)hb;                 // fp16 view of the arena

    static bool attr_set = false;
    if (!attr_set) {
        cudaFuncSetAttribute(mm_hmma, cudaFuncAttributeMaxDynamicSharedMemorySize, MMX_SMEM);
        cudaFuncSetAttribute(flash_k, cudaFuncAttributeMaxDynamicSharedMemorySize, FL_SMEM);
        attr_set = true;
    }

    const int nDD = D_ * D_;
    const int nUP = HID_ * D_;

    // weight prep
    reset_k<<<1, 32>>>();
    absmax_all<<<2048, 256>>>(wq, wk, wv, wo, su, sv, wup, wdn);
    fuse_stalk_q<<<dim3(D_ / 64, H_), 256>>>(su, wq, eqkv, 4, 0, 0);
    fuse_stalk_q<<<dim3(D_ / 64, H_), 256>>>(sv, wk, eqkv, 5, 1, 1024);
    quant_half_k<<<(nDD + 255) / 256, 256>>>(wv, eqkv, D_, 2, nDD, 2048);
    quant_half_k<<<(nDD + 255) / 256, 256>>>(wo, ewo, D_, 3, nDD, 0);
    quant_half_k<<<(nUP + 255) / 256, 256>>>(wup, eup, D_, 6, nUP, 0);
    quant_half_k<<<(nUP + 255) / 256, 256>>>(wdn, edn, HID_, 7, nUP, 0);

    // attention half
    ln_half_k<<<NTOK, 256>>>(x, n1g, n1b, ex);
    mm_hmma<<<dim3(24, 32), 256, MMX_SMEM>>>(ex, eqkv, nullptr, nullptr, hbh, NTOK, 3 * D_, D_);
    flash_k<<<dim3(8, 64), 256, FL_SMEM>>>(hbh, ps, ex);
    mm_hmma<<<dim3(8, 32), 256, MMX_SMEM>>>(ex, ewo, x, out, nullptr, NTOK, D_, D_);

    // MLP half
    ln_half_k<<<NTOK, 256>>>(out, n2g, n2b, ex);
    mm_hmma<<<dim3(24, 32), 256, MMX_SMEM>>>(ex, eup, nullptr, nullptr, hbh, NTOK, HID_, D_);
    rot_half_k<<<NTOK, 256>>>(hbh, th, mng, mnb, eh);
    mm_hmma<<<dim3(8, 32), 256, MMX_SMEM>>>(eh, edn, out, out, nullptr, NTOK, D_, HID_);
}

// round 16
// speedup vs baseline: 2.3302x; 1.0399x over previous
#include <cuda_runtime.h>
#include <cuda_fp16.h>
#include <math.h>
#include <stdint.h>

// ---------------- problem constants ----------------
#define B_ 4
#define T_ 1024
#define D_ 1024
#define H_ 16
#define S_ 64
#define HID_ 3072
#define NTOK (B_*T_)            // 4096

// ---------------- device scratch ----------------
__device__ float g_h[(size_t)NTOK*HID_];     // byte arena: fp16 QKV / fp16 mlp-hidden
__device__ unsigned g_maxabs[8];

// fp16 buffers
__device__ __half e_x  [(size_t)NTOK*D_];          // activations
__device__ __half e_h  [(size_t)NTOK*HID_];        // rot output (down-GEMM A)
__device__ __half e_qkv[(size_t)(3*D_)*D_];        // fused QKV weights
__device__ __half e_wo [(size_t)D_*D_];
__device__ __half e_up [(size_t)HID_*D_];
__device__ __half e_dn [(size_t)D_*HID_];

// ---------------- PTX helpers ----------------
__device__ __forceinline__ uint32_t s2u(const void* p) {
    uint32_t a;
    asm("{ .reg .u64 t; cvta.to.shared.u64 t, %1; cvt.u32.u64 %0, t; }" : "=r"(a) : "l"(p));
    return a;
}
__device__ __forceinline__ void ldsm4(uint32_t* r, uint32_t a) {
    asm volatile("ldmatrix.sync.aligned.m8n8.x4.shared.b16 {%0,%1,%2,%3}, [%4];"
        : "=r"(r[0]), "=r"(r[1]), "=r"(r[2]), "=r"(r[3]) : "r"(a));
}
__device__ __forceinline__ void ldsm4t(uint32_t* r, uint32_t a) {
    asm volatile("ldmatrix.sync.aligned.m8n8.x4.trans.shared.b16 {%0,%1,%2,%3}, [%4];"
        : "=r"(r[0]), "=r"(r[1]), "=r"(r[2]), "=r"(r[3]) : "r"(a));
}
__device__ __forceinline__ void mma16816(float* c, const uint32_t* a, const uint32_t* b) {
    asm volatile("mma.sync.aligned.m16n8k16.row.col.f32.f16.f16.f32 "
        "{%0,%1,%2,%3}, {%4,%5,%6,%7}, {%8,%9}, {%0,%1,%2,%3};"
        : "+f"(c[0]), "+f"(c[1]), "+f"(c[2]), "+f"(c[3])
        : "r"(a[0]), "r"(a[1]), "r"(a[2]), "r"(a[3]), "r"(b[0]), "r"(b[1]));
}
__device__ __forceinline__ void cpasync16(uint32_t dst, const void* src) {
    asm volatile("cp.async.cg.shared.global [%0], [%1], 16;" :: "r"(dst), "l"(src));
}
__device__ __forceinline__ uint32_t packh(float lo, float hi) {
    uint32_t r;
    asm("cvt.rn.f16x2.f32 %0, %1, %2;" : "=r"(r) : "f"(hi), "f"(lo));
    return r;
}

// ---------------- fp16 HMMA GEMM (unchanged from R13) ----------------
#define MMX_SMEM 65536
__global__ __launch_bounds__(256) void mm_hmma(const __half* __restrict__ Ag,
                                               const __half* __restrict__ Bg,
                                               const float* __restrict__ Res,
                                               float* __restrict__ C,
                                               __half* __restrict__ Ch,
                                               int M, int N, int K) {
    extern __shared__ char sm_[];
    uint32_t sbase = s2u(sm_);
    int tid = threadIdx.x, lane = tid & 31, wid = tid >> 5;
    int wm = wid >> 2, wn = wid & 3;
    int m0 = blockIdx.y * 128, n0 = blockIdx.x * 128;
    const __half* Ap = Ag + (size_t)m0 * K;
    const __half* Bp = Bg + (size_t)n0 * K;
    int NC = K >> 6;

    float c[4][4][4];
    #pragma unroll
    for (int i = 0; i < 4; ++i)
        #pragma unroll
        for (int j = 0; j < 4; ++j)
            #pragma unroll
            for (int e = 0; e < 4; ++e) c[i][j][e] = 0.f;

    int crow = tid >> 3, cch = tid & 7;

    #define COPY_CHUNK(cidx, buf) do {                                             \
        uint32_t Ab_ = sbase + (buf) * 32768;                                      \
        uint32_t Bb_ = Ab_ + 16384;                                                \
        int kc_ = (cidx) << 6;                                                     \
        _Pragma("unroll")                                                          \
        for (int i_ = 0; i_ < 4; ++i_) {                                           \
            int row_ = crow + i_ * 32;                                             \
            uint32_t dst_ = Ab_ + row_ * 128 + (((cch) ^ (row_ & 7)) << 4);        \
            cpasync16(dst_, Ap + (size_t)row_ * K + kc_ + cch * 8);                \
        }                                                                          \
        _Pragma("unroll")                                                          \
        for (int i_ = 0; i_ < 4; ++i_) {                                           \
            int row_ = crow + i_ * 32;                                             \
            uint32_t dst_ = Bb_ + row_ * 128 + (((cch) ^ (row_ & 7)) << 4);        \
            cpasync16(dst_, Bp + (size_t)row_ * K + kc_ + cch * 8);                \
        }                                                                          \
        asm volatile("cp.async.commit_group;" ::: "memory");                       \
    } while (0)

    COPY_CHUNK(0, 0);
    for (int c0 = 0; c0 < NC; ++c0) {
        int buf = c0 & 1;
        if (c0 + 1 < NC) {
            COPY_CHUNK(c0 + 1, buf ^ 1);
            asm volatile("cp.async.wait_group 1;" ::: "memory");
        } else {
            asm volatile("cp.async.wait_group 0;" ::: "memory");
        }
        __syncthreads();
        uint32_t Ab = sbase + buf * 32768;
        uint32_t Bb = Ab + 16384;
        #pragma unroll
        for (int ks = 0; ks < 4; ++ks) {
            uint32_t a[4][4], b[2][4];
            #pragma unroll
            for (int i = 0; i < 4; ++i) {
                int row = wm * 64 + i * 16 + (lane & 15);
                int ch = ks * 2 + (lane >> 4);
                ldsm4(a[i], Ab + row * 128 + ((ch ^ (row & 7)) << 4));
            }
            #pragma unroll
            for (int jq = 0; jq < 2; ++jq) {
                int row = wn * 32 + jq * 16 + ((lane >> 4) & 1) * 8 + (lane & 7);
                int ch = ks * 2 + ((lane >> 3) & 1);
                ldsm4(b[jq], Bb + row * 128 + ((ch ^ (row & 7)) << 4));
            }
            #pragma unroll
            for (int i = 0; i < 4; ++i)
                #pragma unroll
                for (int j = 0; j < 4; ++j)
                    mma16816(c[i][j], a[i], &b[j >> 1][(j & 1) * 2]);
        }
        __syncthreads();
    }
    #undef COPY_CHUNK

    int g = lane >> 2, tg = lane & 3;
    if (Ch) {
        #pragma unroll
        for (int i = 0; i < 4; ++i) {
            int r0 = m0 + wm * 64 + i * 16 + g;
            #pragma unroll
            for (int j = 0; j < 4; ++j) {
                int cc = n0 + wn * 32 + j * 8 + tg * 2;
                *(__half2*)(Ch + (size_t)r0 * N + cc) =
                    __halves2half2(__float2half(c[i][j][0]), __float2half(c[i][j][1]));
                *(__half2*)(Ch + (size_t)(r0 + 8) * N + cc) =
                    __halves2half2(__float2half(c[i][j][2]), __float2half(c[i][j][3]));
            }
        }
    } else {
        #pragma unroll
        for (int i = 0; i < 4; ++i) {
            int r0 = m0 + wm * 64 + i * 16 + g;
            #pragma unroll
            for (int j = 0; j < 4; ++j) {
                int cc = n0 + wn * 32 + j * 8 + tg * 2;
                float* p0 = C + (size_t)r0 * N + cc;
                float* p1 = C + (size_t)(r0 + 8) * N + cc;
                if (Res) {
                    float2 v0 = *(const float2*)(Res + (size_t)r0 * N + cc);
                    float2 v1 = *(const float2*)(Res + (size_t)(r0 + 8) * N + cc);
                    *(float2*)p0 = make_float2(c[i][j][0] + v0.x, c[i][j][1] + v0.y);
                    *(float2*)p1 = make_float2(c[i][j][2] + v1.x, c[i][j][3] + v1.y);
                } else {
                    *(float2*)p0 = make_float2(c[i][j][0], c[i][j][1]);
                    *(float2*)p1 = make_float2(c[i][j][2], c[i][j][3]);
                }
            }
        }
    }
}

// ---------------- fused flash attention (unchanged from R13) ----------------
#define FL_SMEM 36864
__global__ __launch_bounds__(256, 2) void flash_k(const __half* __restrict__ qkv,
                                                  const float* __restrict__ p_scale,
                                                  __half* __restrict__ exo) {
    extern __shared__ char sm_[];
    uint32_t sb = s2u(sm_);
    const uint32_t sQ = sb, sK = sb + 18432, sVh = sb + 27648;

    int tid = threadIdx.x, lane = tid & 31, wid = tid >> 5;
    int qt = 7 - (int)blockIdx.x;
    int bh = blockIdx.y, b = bh >> 4, h = bh & 15;

    const __half* Qg = qkv + ((size_t)(b * T_ + qt * 128)) * 3072 + h * 64;
    const __half* Kg = qkv + (size_t)(b * T_) * 3072 + 1024 + h * 64;
    const __half* Vg = qkv + (size_t)(b * T_) * 3072 + 2048 + h * 64;

    #pragma unroll
    for (int i = 0; i < 4; ++i) {
        int idx = tid + i * 256;
        int r = idx >> 3, cc = idx & 7;
        cpasync16(sQ + r * 144 + cc * 16, Qg + (size_t)r * 3072 + cc * 8);
    }
    asm volatile("cp.async.commit_group;" ::: "memory");

    float m0 = -INFINITY, m1 = -INFINITY, l0 = 0.f, l1 = 0.f;
    float O[8][4];
    #pragma unroll
    for (int j = 0; j < 8; ++j)
        #pragma unroll
        for (int e = 0; e < 4; ++e) O[j][e] = 0.f;

    float ps = p_scale[0];
    int g = lane >> 2, tg = lane & 3;
    int wr0 = wid * 16;
    int row_g0 = qt * 128 + wr0 + g;
    int nch = (qt * 128 + 128) >> 6;

    uint32_t aq_base = sQ + (wr0 + (lane & 15)) * 144 + (lane >> 4) * 16;
    uint32_t bk_base = sK + (((lane >> 3) & 2) * 4 + (lane & 7)) * 144 + ((lane >> 3) & 1) * 16;
    uint32_t v_roff = ((lane & 7) + ((lane >> 3) & 1) * 8) * 144 + ((lane >> 4) & 1) * 16;

    for (int ch = 0; ch < nch; ++ch) {
        int u0 = ch << 6;
        __syncthreads();
        #pragma unroll
        for (int i = 0; i < 2; ++i) {
            int idx = tid + i * 256;
            int r = idx >> 3, cc = idx & 7;
            cpasync16(sK + r * 144 + cc * 16, Kg + (size_t)(u0 + r) * 3072 + cc * 8);
            cpasync16(sVh + r * 144 + cc * 16, Vg + (size_t)(u0 + r) * 3072 + cc * 8);
        }
        asm volatile("cp.async.commit_group;" ::: "memory");
        asm volatile("cp.async.wait_group 0;" ::: "memory");
        __syncthreads();

        float c[8][4];
        #pragma unroll
        for (int j = 0; j < 8; ++j)
            #pragma unroll
            for (int e = 0; e < 4; ++e) c[j][e] = 0.f;
        #pragma unroll
        for (int ks = 0; ks < 4; ++ks) {
            uint32_t a[4];
            ldsm4(a, aq_base + ks * 32);
            #pragma unroll
            for (int jp = 0; jp < 4; ++jp) {
                uint32_t bb[4];
                ldsm4(bb, bk_base + jp * 16 * 144 + ks * 32);
                mma16816(c[jp * 2], a, bb);
                mma16816(c[jp * 2 + 1], a, bb + 2);
            }
        }

        #pragma unroll
        for (int j = 0; j < 8; ++j) {
            int ub = u0 + j * 8 + tg * 2;
            #pragma unroll
            for (int e = 0; e < 4; ++e) {
                int row = row_g0 + (e >> 1) * 8;
                int u = ub + (e & 1);
                int d = row - u;
                if (d < 0) c[j][e] = -INFINITY;
                else {
                    float bias;
                    if (d == 0) bias = 1.f;
                    else {
                        int vp = __ffs(d) - 1;
                        vp = vp > 16 ? 16 : vp;
                        bias = (float)vp * (1.f / 16.f);
                    }
                    c[j][e] = c[j][e] * 0.125f + ps * bias;
                }
            }
        }

        float mx0 = -INFINITY, mx1 = -INFINITY;
        #pragma unroll
        for (int j = 0; j < 8; ++j) {
            mx0 = fmaxf(mx0, fmaxf(c[j][0], c[j][1]));
            mx1 = fmaxf(mx1, fmaxf(c[j][2], c[j][3]));
        }
        mx0 = fmaxf(mx0, __shfl_xor_sync(0xffffffffu, mx0, 1));
        mx0 = fmaxf(mx0, __shfl_xor_sync(0xffffffffu, mx0, 2));
        mx1 = fmaxf(mx1, __shfl_xor_sync(0xffffffffu, mx1, 1));
        mx1 = fmaxf(mx1, __shfl_xor_sync(0xffffffffu, mx1, 2));
        float mn0 = fmaxf(m0, mx0), mn1 = fmaxf(m1, mx1);
        float al0 = __expf(m0 - mn0), al1 = __expf(m1 - mn1);
        float s0 = 0.f, s1 = 0.f;
        #pragma unroll
        for (int j = 0; j < 8; ++j) {
            c[j][0] = __expf(c[j][0] - mn0);
            c[j][1] = __expf(c[j][1] - mn0);
            c[j][2] = __expf(c[j][2] - mn1);
            c[j][3] = __expf(c[j][3] - mn1);
            s0 += c[j][0] + c[j][1];
            s1 += c[j][2] + c[j][3];
        }
        s0 += __shfl_xor_sync(0xffffffffu, s0, 1);
        s0 += __shfl_xor_sync(0xffffffffu, s0, 2);
        s1 += __shfl_xor_sync(0xffffffffu, s1, 1);
        s1 += __shfl_xor_sync(0xffffffffu, s1, 2);
        l0 = l0 * al0 + s0;
        l1 = l1 * al1 + s1;
        #pragma unroll
        for (int j = 0; j < 8; ++j) {
            O[j][0] *= al0; O[j][1] *= al0;
            O[j][2] *= al1; O[j][3] *= al1;
        }
        m0 = mn0; m1 = mn1;

        #pragma unroll
        for (int ms = 0; ms < 4; ++ms) {
            uint32_t ah[4];
            ah[0] = packh(c[2 * ms][0], c[2 * ms][1]);
            ah[1] = packh(c[2 * ms][2], c[2 * ms][3]);
            ah[2] = packh(c[2 * ms + 1][0], c[2 * ms + 1][1]);
            ah[3] = packh(c[2 * ms + 1][2], c[2 * ms + 1][3]);
            uint32_t vaddr = v_roff + ms * 16 * 144;
            #pragma unroll
            for (int jp = 0; jp < 4; ++jp) {
                uint32_t vh[4];
                ldsm4t(vh, sVh + vaddr + jp * 32);
                mma16816(O[jp * 2],     ah, vh);
                mma16816(O[jp * 2 + 1], ah, vh + 2);
            }
        }
    }

    __syncthreads();
    float* Of = (float*)sm_;
    float i0 = 1.f / l0, i1 = 1.f / l1;
    #pragma unroll
    for (int j = 0; j < 8; ++j) {
        int cc = j * 8 + tg * 2;
        Of[(wr0 + g) * 66 + cc]     = O[j][0] * i0;
        Of[(wr0 + g) * 66 + cc + 1] = O[j][1] * i0;
        Of[(wr0 + g + 8) * 66 + cc]     = O[j][2] * i1;
        Of[(wr0 + g + 8) * 66 + cc + 1] = O[j][3] * i1;
    }
    __syncthreads();
    #pragma unroll
    for (int i = 0; i < 16; ++i) {
        int idx2 = tid + i * 256;
        int r = idx2 >> 5, c2 = (idx2 & 31) * 2;
        float v0 = Of[r * 66 + c2], v1 = Of[r * 66 + c2 + 1];
        int tok = b * T_ + qt * 128 + r;
        size_t base = (size_t)tok * 1024 + h * 64 + c2;
        *(__half2*)(exo + base) = __halves2half2(__float2half(v0), __float2half(v1));
    }
}

// ---------------- reductions / prep ----------------
__device__ __forceinline__ float2 block_reduce2(float a, float b) {
    #pragma unroll
    for (int o = 16; o; o >>= 1) {
        a += __shfl_xor_sync(0xffffffffu, a, o);
        b += __shfl_xor_sync(0xffffffffu, b, o);
    }
    __shared__ float sa[8], sb2[8];
    int w = threadIdx.x >> 5, l = threadIdx.x & 31;
    int nw = (blockDim.x + 31) >> 5;
    if (l == 0) { sa[w] = a; sb2[w] = b; }
    __syncthreads();
    if (w == 0) {
        a = (l < nw) ? sa[l] : 0.f;
        b = (l < nw) ? sb2[l] : 0.f;
        #pragma unroll
        for (int o = 4; o; o >>= 1) {
            a += __shfl_xor_sync(0xffffffffu, a, o);
            b += __shfl_xor_sync(0xffffffffu, b, o);
        }
        if (l == 0) { sa[0] = a; sb2[0] = b; }
    }
    __syncthreads();
    return make_float2(sa[0], sb2[0]);
}

__global__ void reset_k() {
    if (threadIdx.x < 8) g_maxabs[threadIdx.x] = 0u;
}

__global__ __launch_bounds__(256) void absmax_all(const float* wq, const float* wk,
                                                  const float* wv, const float* wo,
                                                  const float* su, const float* sv,
                                                  const float* wup, const float* wdn) {
    int seg = blockIdx.x >> 8, blk = blockIdx.x & 255;
    const float* p; int n;
    switch (seg) {
        case 0: p = wq;  n = D_ * D_;   break;
        case 1: p = wk;  n = D_ * D_;   break;
        case 2: p = wv;  n = D_ * D_;   break;
        case 3: p = wo;  n = D_ * D_;   break;
        case 4: p = su;  n = S_ * S_;   break;
        case 5: p = sv;  n = S_ * S_;   break;
        case 6: p = wup; n = HID_ * D_; break;
        default: p = wdn; n = HID_ * D_; break;
    }
    const float4* p4 = (const float4*)p;
    int n4 = n >> 2;
    float m = 0.f;
    for (int i = blk * 256 + threadIdx.x; i < n4; i += 256 * 256) {
        float4 v = p4[i];
        m = fmaxf(m, fmaxf(fmaxf(fabsf(v.x), fabsf(v.y)), fmaxf(fabsf(v.z), fabsf(v.w))));
    }
    #pragma unroll
    for (int o = 16; o; o >>= 1) m = fmaxf(m, __shfl_xor_sync(0xffffffffu, m, o));
    __shared__ float sm[8];
    if ((threadIdx.x & 31) == 0) sm[threadIdx.x >> 5] = m;
    __syncthreads();
    if (threadIdx.x < 8) {
        m = sm[threadIdx.x];
        #pragma unroll
        for (int o = 4; o; o >>= 1) m = fmaxf(m, __shfl_xor_sync(0xffu, m, o));
        if (threadIdx.x == 0) atomicMax(&g_maxabs[seg], __float_as_uint(m));
    }
}

// quantize -> fp16 single tensor
__global__ __launch_bounds__(256) void quant_half_k(const float* __restrict__ w,
                                                    __half* __restrict__ out,
                                                    int K, int slot, int total, int rowoff) {
    float scale = __uint_as_float(g_maxabs[slot]) / 31.0f + 1e-8f;
    int idx = blockIdx.x * blockDim.x + threadIdx.x;
    if (idx >= total) return;
    float q = rintf(w[idx] / scale);
    q = fminf(fmaxf(q, -31.f), 31.f);
    out[(size_t)rowoff * K + idx] = __float2half(q * scale);
}

// merged quantize for wo, wup, wdn (segmented by blockIdx)
__global__ __launch_bounds__(256) void quant3_k(const float* __restrict__ wo, __half* __restrict__ ewo,
                                                const float* __restrict__ wup, __half* __restrict__ eup,
                                                const float* __restrict__ wdn, __half* __restrict__ edn) {
    const int nDD4 = (D_ * D_) / 256;         // 4096 blocks
    const int nUP4 = (HID_ * D_) / 256;       // 12288 blocks
    int bx = blockIdx.x;
    const float* src; __half* dst; int slot; int idx;
    if (bx < nDD4) { src = wo; dst = ewo; slot = 3; idx = bx * 256 + threadIdx.x; }
    else if (bx < nDD4 + nUP4) { src = wup; dst = eup; slot = 6; idx = (bx - nDD4) * 256 + threadIdx.x; }
    else { src = wdn; dst = edn; slot = 7; idx = (bx - nDD4 - nUP4) * 256 + threadIdx.x; }
    float scale = __uint_as_float(g_maxabs[slot]) / 31.0f + 1e-8f;
    float q = rintf(src[idx] / scale);
    q = fminf(fmaxf(q, -31.f), 31.f);
    dst[idx] = __float2half(q * scale);
}

// fw[h*64+s][k] = sum_j q(su)[s][j] * q(w)[h*64+j][k], fp16 out, register-blocked
__global__ __launch_bounds__(256) void fuse_stalk_q(const float* __restrict__ su,
                                                    const float* __restrict__ w,
                                                    __half* __restrict__ out,
                                                    int slot_s, int slot_w, int rowoff) {
    __shared__ float Ws[64][68];
    __shared__ float Ss[64][68];
    float sc_s = __uint_as_float(g_maxabs[slot_s]) / 31.0f + 1e-8f;
    float sc_w = __uint_as_float(g_maxabs[slot_w]) / 31.0f + 1e-8f;
    int h = blockIdx.y;
    int k0 = blockIdx.x * 64;
    int tid = threadIdx.x;
    #pragma unroll
    for (int it = 0; it < 4; ++it) {
        int chunk = tid + it * 256;
        int r = chunk >> 4, c4 = (chunk & 15) * 4;
        float4 v = *(const float4*)(w + (size_t)(h * 64 + r) * D_ + k0 + c4);
        Ws[r][c4 + 0] = fminf(fmaxf(rintf(v.x / sc_w), -31.f), 31.f) * sc_w;
        Ws[r][c4 + 1] = fminf(fmaxf(rintf(v.y / sc_w), -31.f), 31.f) * sc_w;
        Ws[r][c4 + 2] = fminf(fmaxf(rintf(v.z / sc_w), -31.f), 31.f) * sc_w;
        Ws[r][c4 + 3] = fminf(fmaxf(rintf(v.w / sc_w), -31.f), 31.f) * sc_w;
    }
    #pragma unroll
    for (int it = 0; it < 4; ++it) {
        int chunk = tid + it * 256;
        int r = chunk >> 4, c4 = (chunk & 15) * 4;
        float4 v = *(const float4*)(su + (size_t)r * 64 + c4);
        Ss[r][c4 + 0] = fminf(fmaxf(rintf(v.x / sc_s), -31.f), 31.f) * sc_s;
        Ss[r][c4 + 1] = fminf(fmaxf(rintf(v.y / sc_s), -31.f), 31.f) * sc_s;
        Ss[r][c4 + 2] = fminf(fmaxf(rintf(v.z / sc_s), -31.f), 31.f) * sc_s;
        Ss[r][c4 + 3] = fminf(fmaxf(rintf(v.w / sc_s), -31.f), 31.f) * sc_s;
    }
    __syncthreads();
    int kk = (tid & 15) * 4, s0 = tid >> 4;
    float acc[4][4];
    #pragma unroll
    for (int m = 0; m < 4; ++m)
        #pragma unroll
        for (int q = 0; q < 4; ++q) acc[m][q] = 0.f;
    #pragma unroll 8
    for (int j = 0; j < 64; ++j) {
        float4 wv4 = *(const float4*)&Ws[j][kk];
        float sv0 = Ss[s0][j], sv1 = Ss[s0 + 16][j], sv2 = Ss[s0 + 32][j], sv3 = Ss[s0 + 48][j];
        acc[0][0] += sv0 * wv4.x; acc[0][1] += sv0 * wv4.y; acc[0][2] += sv0 * wv4.z; acc[0][3] += sv0 * wv4.w;
        acc[1][0] += sv1 * wv4.x; acc[1][1] += sv1 * wv4.y; acc[1][2] += sv1 * wv4.z; acc[1][3] += sv1 * wv4.w;
        acc[2][0] += sv2 * wv4.x; acc[2][1] += sv2 * wv4.y; acc[2][2] += sv2 * wv4.z; acc[2][3] += sv2 * wv4.w;
        acc[3][0] += sv3 * wv4.x; acc[3][1] += sv3 * wv4.y; acc[3][2] += sv3 * wv4.z; acc[3][3] += sv3 * wv4.w;
    }
    #pragma unroll
    for (int m = 0; m < 4; ++m) {
        size_t row = (size_t)(rowoff + h * 64 + s0 + m * 16);
        __half2 o0 = __halves2half2(__float2half(acc[m][0]), __float2half(acc[m][1]));
        __half2 o1 = __halves2half2(__float2half(acc[m][2]), __float2half(acc[m][3]));
        *(__half2*)(out + row * D_ + k0 + kk)     = o0;
        *(__half2*)(out + row * D_ + k0 + kk + 2) = o1;
    }
}

// layernorm(D) -> fp16
__global__ __launch_bounds__(256) void ln_half_k(const float* __restrict__ x,
                                                 const float* __restrict__ g,
                                                 const float* __restrict__ bb,
                                                 __half* __restrict__ out) {
    int row = blockIdx.x;
    const float* xr = x + (size_t)row * D_;
    int c = threadIdx.x * 4;
    float4 v = *(const float4*)(xr + c);
    float s = v.x + v.y + v.z + v.w;
    float sq = v.x * v.x + v.y * v.y + v.z * v.z + v.w * v.w;
    float2 r = block_reduce2(s, sq);
    float mu = r.x * (1.0f / D_);
    float var = r.y * (1.0f / D_) - mu * mu;
    float inv = rsqrtf(var + 1e-5f);
    float4 gg = *(const float4*)(g + c);
    float4 bv = *(const float4*)(bb + c);
    __half2 o0 = __halves2half2(__float2half((v.x - mu) * inv * gg.x + bv.x),
                                __float2half((v.y - mu) * inv * gg.y + bv.y));
    __half2 o1 = __halves2half2(__float2half((v.z - mu) * inv * gg.z + bv.z),
                                __float2half((v.w - mu) * inv * gg.w + bv.w));
    *(__half2*)(out + (size_t)row * D_ + c)     = o0;
    *(__half2*)(out + (size_t)row * D_ + c + 2) = o1;
}

// SO(2) rotate + layernorm(HID) + SiLU -> fp16 (fp16 input)
__global__ __launch_bounds__(256) void rot_half_k(const __half* __restrict__ hin,
                                                  const float* __restrict__ theta,
                                                  const float* __restrict__ g,
                                                  const float* __restrict__ bb,
                                                  __half* __restrict__ out) {
    int row = blockIdx.x;
    const __half* hrow = hin + (size_t)row * HID_;
    int tid = threadIdx.x;
    float r0[6], r1[6];
    float s = 0.f, sq = 0.f;
    #pragma unroll
    for (int i = 0; i < 6; ++i) {
        int p = tid + i * 256;
        __half2 ab2 = *(const __half2*)(hrow + 2 * p);
        float ax = __half2float(__low2half(ab2));
        float ay = __half2float(__high2half(ab2));
        float sn, cs;
        sincosf(theta[p], &sn, &cs);
        r0[i] = cs * ax - sn * ay;
        r1[i] = sn * ax + cs * ay;
        s += r0[i] + r1[i];
        sq += r0[i] * r0[i] + r1[i] * r1[i];
    }
    float2 r = block_reduce2(s, sq);
    float mu = r.x * (1.0f / HID_);
    float var = r.y * (1.0f / HID_) - mu * mu;
    float inv = rsqrtf(var + 1e-5f);
    size_t base = (size_t)row * HID_;
    #pragma unroll
    for (int i = 0; i < 6; ++i) {
        int p = tid + i * 256;
        int e0 = 2 * p, e1 = 2 * p + 1;
        float y0 = (r0[i] - mu) * inv * g[e0] + bb[e0];
        float y1 = (r1[i] - mu) * inv * g[e1] + bb[e1];
        y0 = y0 / (1.0f + __expf(-y0));
        y1 = y1 / (1.0f + __expf(-y1));
        *(__half2*)(out + base + e0) = __halves2half2(__float2half(y0), __float2half(y1));
    }
}

// ---------------- host launcher ----------------
extern "C" void kernel_launch(void* const* d_in, const int* in_sizes, int n_in,
                              void* d_out, int out_size) {
    const float* x   = (const float*)d_in[0];
    const float* wq  = (const float*)d_in[1];
    const float* wk  = (const float*)d_in[2];
    const float* wv  = (const float*)d_in[3];
    const float* wo  = (const float*)d_in[4];
    const float* su  = (const float*)d_in[5];
    const float* sv  = (const float*)d_in[6];
    const float* ps  = (const float*)d_in[7];
    const float* n1g = (const float*)d_in[8];
    const float* n1b = (const float*)d_in[9];
    const float* n2g = (const float*)d_in[10];
    const float* n2b = (const float*)d_in[11];
    const float* wup = (const float*)d_in[12];
    const float* wdn = (const float*)d_in[13];
    const float* th  = (const float*)d_in[14];
    const float* mng = (const float*)d_in[15];
    const float* mnb = (const float*)d_in[16];
    float* out = (float*)d_out;

    float* hb;
    __half *ex, *eh, *eqkv, *ewo, *eup, *edn;
    cudaGetSymbolAddress((void**)&hb, g_h);
    cudaGetSymbolAddress((void**)&ex, e_x);
    cudaGetSymbolAddress((void**)&eh, e_h);
    cudaGetSymbolAddress((void**)&eqkv, e_qkv);
    cudaGetSymbolAddress((void**)&ewo, e_wo);
    cudaGetSymbolAddress((void**)&eup, e_up);
    cudaGetSymbolAddress((void**)&edn, e_dn);
    __half* hbh = (__half*)hb;

    static bool init_done = false;
    static cudaStream_t s1, s2, s3;
    static cudaEvent_t evStart, evA, evQ1, evQ2, evWV, evW3;
    if (!init_done) {
        cudaFuncSetAttribute(mm_hmma, cudaFuncAttributeMaxDynamicSharedMemorySize, MMX_SMEM);
        cudaFuncSetAttribute(flash_k, cudaFuncAttributeMaxDynamicSharedMemorySize, FL_SMEM);
        cudaStreamCreateWithFlags(&s1, cudaStreamNonBlocking);
        cudaStreamCreateWithFlags(&s2, cudaStreamNonBlocking);
        cudaStreamCreateWithFlags(&s3, cudaStreamNonBlocking);
        cudaEventCreateWithFlags(&evStart, cudaEventDisableTiming);
        cudaEventCreateWithFlags(&evA, cudaEventDisableTiming);
        cudaEventCreateWithFlags(&evQ1, cudaEventDisableTiming);
        cudaEventCreateWithFlags(&evQ2, cudaEventDisableTiming);
        cudaEventCreateWithFlags(&evWV, cudaEventDisableTiming);
        cudaEventCreateWithFlags(&evW3, cudaEventDisableTiming);
        init_done = true;
    }

    const int nDD = D_ * D_;
    const int nUP = HID_ * D_;

    // fork side streams from the capture-origin stream
    cudaEventRecord(evStart, 0);
    cudaStreamWaitEvent(s1, evStart, 0);

    // ---- prep branch (s1 -> fan out to s2/s3) ----
    reset_k<<<1, 32, 0, s1>>>();
    absmax_all<<<2048, 256, 0, s1>>>(wq, wk, wv, wo, su, sv, wup, wdn);
    cudaEventRecord(evA, s1);
    cudaStreamWaitEvent(s2, evA, 0);
    cudaStreamWaitEvent(s3, evA, 0);

    fuse_stalk_q<<<dim3(D_ / 64, H_), 256, 0, s1>>>(su, wq, eqkv, 4, 0, 0);
    cudaEventRecord(evQ1, s1);
    fuse_stalk_q<<<dim3(D_ / 64, H_), 256, 0, s2>>>(sv, wk, eqkv, 5, 1, 1024);
    cudaEventRecord(evQ2, s2);
    quant_half_k<<<(nDD + 255) / 256, 256, 0, s3>>>(wv, eqkv, D_, 2, nDD, 2048);
    cudaEventRecord(evWV, s3);
    quant3_k<<<(nDD + 2 * nUP) / 256, 256, 0, s3>>>(wo, ewo, wup, eup, wdn, edn);
    cudaEventRecord(evW3, s3);

    // ---- main branch (stream 0) ----
    ln_half_k<<<NTOK, 256>>>(x, n1g, n1b, ex);
    cudaStreamWaitEvent(0, evQ1, 0);
    cudaStreamWaitEvent(0, evQ2, 0);
    cudaStreamWaitEvent(0, evWV, 0);
    mm_hmma<<<dim3(24, 32), 256, MMX_SMEM>>>(ex, eqkv, nullptr, nullptr, hbh, NTOK, 3 * D_, D_);
    flash_k<<<dim3(8, 64), 256, FL_SMEM>>>(hbh, ps, ex);
    cudaStreamWaitEvent(0, evW3, 0);        // joins s3; ewo/eup/edn ready
    mm_hmma<<<dim3(8, 32), 256, MMX_SMEM>>>(ex, ewo, x, out, nullptr, NTOK, D_, D_);

    ln_half_k<<<NTOK, 256>>>(out, n2g, n2b, ex);
    mm_hmma<<<dim3(24, 32), 256, MMX_SMEM>>>(ex, eup, nullptr, nullptr, hbh, NTOK, HID_, D_);
    rot_half_k<<<NTOK, 256>>>(hbh, th, mng, mnb, eh);
    mm_hmma<<<dim3(8, 32), 256, MMX_SMEM>>>(eh, edn, out, out, nullptr, NTOK, D_, HID_);
}

// round 17
// speedup vs baseline: 2.3430x; 1.0055x over previous
#include <cuda_runtime.h>
#include <cuda_fp16.h>
#include <math.h>
#include <stdint.h>

// ---------------- problem constants ----------------
#define B_ 4
#define T_ 1024
#define D_ 1024
#define H_ 16
#define S_ 64
#define HID_ 3072
#define NTOK (B_*T_)            // 4096

// ---------------- device scratch ----------------
__device__ float g_h[(size_t)NTOK*HID_];     // byte arena: fp16 QKV / fp16 mlp-hidden
__device__ unsigned g_maxabs[8];

// fp16 buffers
__device__ __half e_x  [(size_t)NTOK*D_];          // activations
__device__ __half e_h  [(size_t)NTOK*HID_];        // rot output (down-GEMM A)
__device__ __half e_qkv[(size_t)(3*D_)*D_];        // fused QKV weights
__device__ __half e_wo [(size_t)D_*D_];
__device__ __half e_up [(size_t)HID_*D_];
__device__ __half e_dn [(size_t)D_*HID_];

// ---------------- PTX helpers ----------------
__device__ __forceinline__ uint32_t s2u(const void* p) {
    uint32_t a;
    asm("{ .reg .u64 t; cvta.to.shared.u64 t, %1; cvt.u32.u64 %0, t; }" : "=r"(a) : "l"(p));
    return a;
}
__device__ __forceinline__ void ldsm4(uint32_t* r, uint32_t a) {
    asm volatile("ldmatrix.sync.aligned.m8n8.x4.shared.b16 {%0,%1,%2,%3}, [%4];"
        : "=r"(r[0]), "=r"(r[1]), "=r"(r[2]), "=r"(r[3]) : "r"(a));
}
__device__ __forceinline__ void ldsm4t(uint32_t* r, uint32_t a) {
    asm volatile("ldmatrix.sync.aligned.m8n8.x4.trans.shared.b16 {%0,%1,%2,%3}, [%4];"
        : "=r"(r[0]), "=r"(r[1]), "=r"(r[2]), "=r"(r[3]) : "r"(a));
}
__device__ __forceinline__ void mma16816(float* c, const uint32_t* a, const uint32_t* b) {
    asm volatile("mma.sync.aligned.m16n8k16.row.col.f32.f16.f16.f32 "
        "{%0,%1,%2,%3}, {%4,%5,%6,%7}, {%8,%9}, {%0,%1,%2,%3};"
        : "+f"(c[0]), "+f"(c[1]), "+f"(c[2]), "+f"(c[3])
        : "r"(a[0]), "r"(a[1]), "r"(a[2]), "r"(a[3]), "r"(b[0]), "r"(b[1]));
}
__device__ __forceinline__ void cpasync16(uint32_t dst, const void* src) {
    asm volatile("cp.async.cg.shared.global [%0], [%1], 16;" :: "r"(dst), "l"(src));
}
__device__ __forceinline__ uint32_t packh(float lo, float hi) {
    uint32_t r;
    asm("cvt.rn.f16x2.f32 %0, %1, %2;" : "=r"(r) : "f"(hi), "f"(lo));
    return r;
}

// ---------------- fp16 HMMA GEMM: 3-stage cp.async pipeline ----------------
// CTA 128x128, 8 warps (2x4), warp tile 64x32, K-chunk 64, 3 smem stages (96 KB).
#define MMX_SMEM 98304
__global__ __launch_bounds__(256, 2) void mm_hmma(const __half* __restrict__ Ag,
                                                  const __half* __restrict__ Bg,
                                                  const float* __restrict__ Res,
                                                  float* __restrict__ C,
                                                  __half* __restrict__ Ch,
                                                  int M, int N, int K) {
    extern __shared__ char sm_[];
    uint32_t sbase = s2u(sm_);
    int tid = threadIdx.x, lane = tid & 31, wid = tid >> 5;
    int wm = wid >> 2, wn = wid & 3;
    int m0 = blockIdx.y * 128, n0 = blockIdx.x * 128;
    const __half* Ap = Ag + (size_t)m0 * K;
    const __half* Bp = Bg + (size_t)n0 * K;
    int NC = K >> 6;

    float c[4][4][4];
    #pragma unroll
    for (int i = 0; i < 4; ++i)
        #pragma unroll
        for (int j = 0; j < 4; ++j)
            #pragma unroll
            for (int e = 0; e < 4; ++e) c[i][j][e] = 0.f;

    int crow = tid >> 3, cch = tid & 7;

    #define COPY_CHUNK(cidx, buf) do {                                             \
        uint32_t Ab_ = sbase + (buf) * 32768;                                      \
        uint32_t Bb_ = Ab_ + 16384;                                                \
        int kc_ = (cidx) << 6;                                                     \
        _Pragma("unroll")                                                          \
        for (int i_ = 0; i_ < 4; ++i_) {                                           \
            int row_ = crow + i_ * 32;                                             \
            uint32_t dst_ = Ab_ + row_ * 128 + (((cch) ^ (row_ & 7)) << 4);        \
            cpasync16(dst_, Ap + (size_t)row_ * K + kc_ + cch * 8);                \
        }                                                                          \
        _Pragma("unroll")                                                          \
        for (int i_ = 0; i_ < 4; ++i_) {                                           \
            int row_ = crow + i_ * 32;                                             \
            uint32_t dst_ = Bb_ + row_ * 128 + (((cch) ^ (row_ & 7)) << 4);        \
            cpasync16(dst_, Bp + (size_t)row_ * K + kc_ + cch * 8);                \
        }                                                                          \
        asm volatile("cp.async.commit_group;" ::: "memory");                       \
    } while (0)

    COPY_CHUNK(0, 0);
    if (NC > 1) COPY_CHUNK(1, 1);
    int buf = 0;
    for (int c0 = 0; c0 < NC; ++c0) {
        if (c0 + 2 < NC) {
            int nb = buf + 2; if (nb >= 3) nb -= 3;
            COPY_CHUNK(c0 + 2, nb);
            asm volatile("cp.async.wait_group 2;" ::: "memory");
        } else if (c0 + 1 < NC) {
            asm volatile("cp.async.wait_group 1;" ::: "memory");
        } else {
            asm volatile("cp.async.wait_group 0;" ::: "memory");
        }
        __syncthreads();
        uint32_t Ab = sbase + buf * 32768;
        uint32_t Bb = Ab + 16384;
        #pragma unroll
        for (int ks = 0; ks < 4; ++ks) {
            uint32_t a[4][4], b[2][4];
            #pragma unroll
            for (int i = 0; i < 4; ++i) {
                int row = wm * 64 + i * 16 + (lane & 15);
                int ch = ks * 2 + (lane >> 4);
                ldsm4(a[i], Ab + row * 128 + ((ch ^ (row & 7)) << 4));
            }
            #pragma unroll
            for (int jq = 0; jq < 2; ++jq) {
                int row = wn * 32 + jq * 16 + ((lane >> 4) & 1) * 8 + (lane & 7);
                int ch = ks * 2 + ((lane >> 3) & 1);
                ldsm4(b[jq], Bb + row * 128 + ((ch ^ (row & 7)) << 4));
            }
            #pragma unroll
            for (int i = 0; i < 4; ++i)
                #pragma unroll
                for (int j = 0; j < 4; ++j)
                    mma16816(c[i][j], a[i], &b[j >> 1][(j & 1) * 2]);
        }
        __syncthreads();
        if (++buf == 3) buf = 0;
    }
    #undef COPY_CHUNK

    int g = lane >> 2, tg = lane & 3;
    if (Ch) {
        #pragma unroll
        for (int i = 0; i < 4; ++i) {
            int r0 = m0 + wm * 64 + i * 16 + g;
            #pragma unroll
            for (int j = 0; j < 4; ++j) {
                int cc = n0 + wn * 32 + j * 8 + tg * 2;
                *(__half2*)(Ch + (size_t)r0 * N + cc) =
                    __halves2half2(__float2half(c[i][j][0]), __float2half(c[i][j][1]));
                *(__half2*)(Ch + (size_t)(r0 + 8) * N + cc) =
                    __halves2half2(__float2half(c[i][j][2]), __float2half(c[i][j][3]));
            }
        }
    } else {
        #pragma unroll
        for (int i = 0; i < 4; ++i) {
            int r0 = m0 + wm * 64 + i * 16 + g;
            #pragma unroll
            for (int j = 0; j < 4; ++j) {
                int cc = n0 + wn * 32 + j * 8 + tg * 2;
                float* p0 = C + (size_t)r0 * N + cc;
                float* p1 = C + (size_t)(r0 + 8) * N + cc;
                if (Res) {
                    float2 v0 = *(const float2*)(Res + (size_t)r0 * N + cc);
                    float2 v1 = *(const float2*)(Res + (size_t)(r0 + 8) * N + cc);
                    *(float2*)p0 = make_float2(c[i][j][0] + v0.x, c[i][j][1] + v0.y);
                    *(float2*)p1 = make_float2(c[i][j][2] + v1.x, c[i][j][3] + v1.y);
                } else {
                    *(float2*)p0 = make_float2(c[i][j][0], c[i][j][1]);
                    *(float2*)p1 = make_float2(c[i][j][2], c[i][j][3]);
                }
            }
        }
    }
}

// ---------------- fused flash attention (K/V double-buffered) ----------------
// smem: Q[128x144B] + 2x K[64x144B] + 2x V[64x144B] = 55296 B
#define FL_SMEM 55296
__global__ __launch_bounds__(256, 2) void flash_k(const __half* __restrict__ qkv,
                                                  const float* __restrict__ p_scale,
                                                  __half* __restrict__ exo) {
    extern __shared__ char sm_[];
    uint32_t sb = s2u(sm_);
    const uint32_t sQ = sb;
    const uint32_t sKb[2] = { sb + 18432, sb + 27648 };
    const uint32_t sVb[2] = { sb + 36864, sb + 46080 };

    int tid = threadIdx.x, lane = tid & 31, wid = tid >> 5;
    int qt = 7 - (int)blockIdx.x;
    int bh = blockIdx.y, b = bh >> 4, h = bh & 15;

    const __half* Qg = qkv + ((size_t)(b * T_ + qt * 128)) * 3072 + h * 64;
    const __half* Kg = qkv + (size_t)(b * T_) * 3072 + 1024 + h * 64;
    const __half* Vg = qkv + (size_t)(b * T_) * 3072 + 2048 + h * 64;

    int nch = (qt * 128 + 128) >> 6;

    // group 0: Q tile + K/V chunk 0
    #pragma unroll
    for (int i = 0; i < 4; ++i) {
        int idx = tid + i * 256;
        int r = idx >> 3, cc = idx & 7;
        cpasync16(sQ + r * 144 + cc * 16, Qg + (size_t)r * 3072 + cc * 8);
    }
    #pragma unroll
    for (int i = 0; i < 2; ++i) {
        int idx = tid + i * 256;
        int r = idx >> 3, cc = idx & 7;
        cpasync16(sKb[0] + r * 144 + cc * 16, Kg + (size_t)r * 3072 + cc * 8);
        cpasync16(sVb[0] + r * 144 + cc * 16, Vg + (size_t)r * 3072 + cc * 8);
    }
    asm volatile("cp.async.commit_group;" ::: "memory");

    float m0 = -INFINITY, m1 = -INFINITY, l0 = 0.f, l1 = 0.f;
    float O[8][4];
    #pragma unroll
    for (int j = 0; j < 8; ++j)
        #pragma unroll
        for (int e = 0; e < 4; ++e) O[j][e] = 0.f;

    float ps = p_scale[0];
    int g = lane >> 2, tg = lane & 3;
    int wr0 = wid * 16;
    int row_g0 = qt * 128 + wr0 + g;

    uint32_t aq_base = sQ + (wr0 + (lane & 15)) * 144 + (lane >> 4) * 16;
    uint32_t bk_off = (((lane >> 3) & 2) * 4 + (lane & 7)) * 144 + ((lane >> 3) & 1) * 16;
    uint32_t v_roff = ((lane & 7) + ((lane >> 3) & 1) * 8) * 144 + ((lane >> 4) & 1) * 16;

    for (int ch = 0; ch < nch; ++ch) {
        int kb = ch & 1;
        // prefetch chunk ch+1 into the other buffer
        if (ch + 1 < nch) {
            int u1 = (ch + 1) << 6, nb = kb ^ 1;
            #pragma unroll
            for (int i = 0; i < 2; ++i) {
                int idx = tid + i * 256;
                int r = idx >> 3, cc = idx & 7;
                cpasync16(sKb[nb] + r * 144 + cc * 16, Kg + (size_t)(u1 + r) * 3072 + cc * 8);
                cpasync16(sVb[nb] + r * 144 + cc * 16, Vg + (size_t)(u1 + r) * 3072 + cc * 8);
            }
            asm volatile("cp.async.commit_group;" ::: "memory");
            asm volatile("cp.async.wait_group 1;" ::: "memory");
        } else {
            asm volatile("cp.async.wait_group 0;" ::: "memory");
        }
        __syncthreads();

        int u0 = ch << 6;
        uint32_t bk_base = sKb[kb] + bk_off;
        uint32_t vbase = sVb[kb] + v_roff;

        float c[8][4];
        #pragma unroll
        for (int j = 0; j < 8; ++j)
            #pragma unroll
            for (int e = 0; e < 4; ++e) c[j][e] = 0.f;
        #pragma unroll
        for (int ks = 0; ks < 4; ++ks) {
            uint32_t a[4];
            ldsm4(a, aq_base + ks * 32);
            #pragma unroll
            for (int jp = 0; jp < 4; ++jp) {
                uint32_t bb[4];
                ldsm4(bb, bk_base + jp * 16 * 144 + ks * 32);
                mma16816(c[jp * 2], a, bb);
                mma16816(c[jp * 2 + 1], a, bb + 2);
            }
        }

        #pragma unroll
        for (int j = 0; j < 8; ++j) {
            int ub = u0 + j * 8 + tg * 2;
            #pragma unroll
            for (int e = 0; e < 4; ++e) {
                int row = row_g0 + (e >> 1) * 8;
                int u = ub + (e & 1);
                int d = row - u;
                if (d < 0) c[j][e] = -INFINITY;
                else {
                    float bias;
                    if (d == 0) bias = 1.f;
                    else {
                        int vp = __ffs(d) - 1;
                        vp = vp > 16 ? 16 : vp;
                        bias = (float)vp * (1.f / 16.f);
                    }
                    c[j][e] = c[j][e] * 0.125f + ps * bias;
                }
            }
        }

        float mx0 = -INFINITY, mx1 = -INFINITY;
        #pragma unroll
        for (int j = 0; j < 8; ++j) {
            mx0 = fmaxf(mx0, fmaxf(c[j][0], c[j][1]));
            mx1 = fmaxf(mx1, fmaxf(c[j][2], c[j][3]));
        }
        mx0 = fmaxf(mx0, __shfl_xor_sync(0xffffffffu, mx0, 1));
        mx0 = fmaxf(mx0, __shfl_xor_sync(0xffffffffu, mx0, 2));
        mx1 = fmaxf(mx1, __shfl_xor_sync(0xffffffffu, mx1, 1));
        mx1 = fmaxf(mx1, __shfl_xor_sync(0xffffffffu, mx1, 2));
        float mn0 = fmaxf(m0, mx0), mn1 = fmaxf(m1, mx1);
        float al0 = __expf(m0 - mn0), al1 = __expf(m1 - mn1);
        float s0 = 0.f, s1 = 0.f;
        #pragma unroll
        for (int j = 0; j < 8; ++j) {
            c[j][0] = __expf(c[j][0] - mn0);
            c[j][1] = __expf(c[j][1] - mn0);
            c[j][2] = __expf(c[j][2] - mn1);
            c[j][3] = __expf(c[j][3] - mn1);
            s0 += c[j][0] + c[j][1];
            s1 += c[j][2] + c[j][3];
        }
        s0 += __shfl_xor_sync(0xffffffffu, s0, 1);
        s0 += __shfl_xor_sync(0xffffffffu, s0, 2);
        s1 += __shfl_xor_sync(0xffffffffu, s1, 1);
        s1 += __shfl_xor_sync(0xffffffffu, s1, 2);
        l0 = l0 * al0 + s0;
        l1 = l1 * al1 + s1;
        #pragma unroll
        for (int j = 0; j < 8; ++j) {
            O[j][0] *= al0; O[j][1] *= al0;
            O[j][2] *= al1; O[j][3] *= al1;
        }
        m0 = mn0; m1 = mn1;

        #pragma unroll
        for (int ms = 0; ms < 4; ++ms) {
            uint32_t ah[4];
            ah[0] = packh(c[2 * ms][0], c[2 * ms][1]);
            ah[1] = packh(c[2 * ms][2], c[2 * ms][3]);
            ah[2] = packh(c[2 * ms + 1][0], c[2 * ms + 1][1]);
            ah[3] = packh(c[2 * ms + 1][2], c[2 * ms + 1][3]);
            uint32_t vaddr = vbase + ms * 16 * 144;
            #pragma unroll
            for (int jp = 0; jp < 4; ++jp) {
                uint32_t vh[4];
                ldsm4t(vh, vaddr + jp * 32);
                mma16816(O[jp * 2],     ah, vh);
                mma16816(O[jp * 2 + 1], ah, vh + 2);
            }
        }
        __syncthreads();          // all warps done with buffer kb before it is refilled
    }

    // epilogue: stage fp32 O in smem, then coalesced fp16 write
    float* Of = (float*)sm_;      // [128][66] = 33792 B
    float i0 = 1.f / l0, i1 = 1.f / l1;
    #pragma unroll
    for (int j = 0; j < 8; ++j) {
        int cc = j * 8 + tg * 2;
        Of[(wr0 + g) * 66 + cc]     = O[j][0] * i0;
        Of[(wr0 + g) * 66 + cc + 1] = O[j][1] * i0;
        Of[(wr0 + g + 8) * 66 + cc]     = O[j][2] * i1;
        Of[(wr0 + g + 8) * 66 + cc + 1] = O[j][3] * i1;
    }
    __syncthreads();
    #pragma unroll
    for (int i = 0; i < 16; ++i) {
        int idx2 = tid + i * 256;
        int r = idx2 >> 5, c2 = (idx2 & 31) * 2;
        float v0 = Of[r * 66 + c2], v1 = Of[r * 66 + c2 + 1];
        int tok = b * T_ + qt * 128 + r;
        size_t base = (size_t)tok * 1024 + h * 64 + c2;
        *(__half2*)(exo + base) = __halves2half2(__float2half(v0), __float2half(v1));
    }
}

// ---------------- reductions / prep ----------------
__device__ __forceinline__ float2 block_reduce2(float a, float b) {
    #pragma unroll
    for (int o = 16; o; o >>= 1) {
        a += __shfl_xor_sync(0xffffffffu, a, o);
        b += __shfl_xor_sync(0xffffffffu, b, o);
    }
    __shared__ float sa[8], sb2[8];
    int w = threadIdx.x >> 5, l = threadIdx.x & 31;
    int nw = (blockDim.x + 31) >> 5;
    if (l == 0) { sa[w] = a; sb2[w] = b; }
    __syncthreads();
    if (w == 0) {
        a = (l < nw) ? sa[l] : 0.f;
        b = (l < nw) ? sb2[l] : 0.f;
        #pragma unroll
        for (int o = 4; o; o >>= 1) {
            a += __shfl_xor_sync(0xffffffffu, a, o);
            b += __shfl_xor_sync(0xffffffffu, b, o);
        }
        if (l == 0) { sa[0] = a; sb2[0] = b; }
    }
    __syncthreads();
    return make_float2(sa[0], sb2[0]);
}

__global__ void reset_k() {
    if (threadIdx.x < 8) g_maxabs[threadIdx.x] = 0u;
}

__global__ __launch_bounds__(256) void absmax_all(const float* wq, const float* wk,
                                                  const float* wv, const float* wo,
                                                  const float* su, const float* sv,
                                                  const float* wup, const float* wdn) {
    int seg = blockIdx.x >> 8, blk = blockIdx.x & 255;
    const float* p; int n;
    switch (seg) {
        case 0: p = wq;  n = D_ * D_;   break;
        case 1: p = wk;  n = D_ * D_;   break;
        case 2: p = wv;  n = D_ * D_;   break;
        case 3: p = wo;  n = D_ * D_;   break;
        case 4: p = su;  n = S_ * S_;   break;
        case 5: p = sv;  n = S_ * S_;   break;
        case 6: p = wup; n = HID_ * D_; break;
        default: p = wdn; n = HID_ * D_; break;
    }
    const float4* p4 = (const float4*)p;
    int n4 = n >> 2;
    float m = 0.f;
    for (int i = blk * 256 + threadIdx.x; i < n4; i += 256 * 256) {
        float4 v = p4[i];
        m = fmaxf(m, fmaxf(fmaxf(fabsf(v.x), fabsf(v.y)), fmaxf(fabsf(v.z), fabsf(v.w))));
    }
    #pragma unroll
    for (int o = 16; o; o >>= 1) m = fmaxf(m, __shfl_xor_sync(0xffffffffu, m, o));
    __shared__ float sm[8];
    if ((threadIdx.x & 31) == 0) sm[threadIdx.x >> 5] = m;
    __syncthreads();
    if (threadIdx.x < 8) {
        m = sm[threadIdx.x];
        #pragma unroll
        for (int o = 4; o; o >>= 1) m = fmaxf(m, __shfl_xor_sync(0xffu, m, o));
        if (threadIdx.x == 0) atomicMax(&g_maxabs[seg], __float_as_uint(m));
    }
}

__global__ __launch_bounds__(256) void quant_half_k(const float* __restrict__ w,
                                                    __half* __restrict__ out,
                                                    int K, int slot, int total, int rowoff) {
    float scale = __uint_as_float(g_maxabs[slot]) / 31.0f + 1e-8f;
    int idx = blockIdx.x * blockDim.x + threadIdx.x;
    if (idx >= total) return;
    float q = rintf(w[idx] / scale);
    q = fminf(fmaxf(q, -31.f), 31.f);
    out[(size_t)rowoff * K + idx] = __float2half(q * scale);
}

__global__ __launch_bounds__(256) void quant3_k(const float* __restrict__ wo, __half* __restrict__ ewo,
                                                const float* __restrict__ wup, __half* __restrict__ eup,
                                                const float* __restrict__ wdn, __half* __restrict__ edn) {
    const int nDD4 = (D_ * D_) / 256;
    const int nUP4 = (HID_ * D_) / 256;
    int bx = blockIdx.x;
    const float* src; __half* dst; int slot; int idx;
    if (bx < nDD4) { src = wo; dst = ewo; slot = 3; idx = bx * 256 + threadIdx.x; }
    else if (bx < nDD4 + nUP4) { src = wup; dst = eup; slot = 6; idx = (bx - nDD4) * 256 + threadIdx.x; }
    else { src = wdn; dst = edn; slot = 7; idx = (bx - nDD4 - nUP4) * 256 + threadIdx.x; }
    float scale = __uint_as_float(g_maxabs[slot]) / 31.0f + 1e-8f;
    float q = rintf(src[idx] / scale);
    q = fminf(fmaxf(q, -31.f), 31.f);
    dst[idx] = __float2half(q * scale);
}

__global__ __launch_bounds__(256) void fuse_stalk_q(const float* __restrict__ su,
                                                    const float* __restrict__ w,
                                                    __half* __restrict__ out,
                                                    int slot_s, int slot_w, int rowoff) {
    __shared__ float Ws[64][68];
    __shared__ float Ss[64][68];
    float sc_s = __uint_as_float(g_maxabs[slot_s]) / 31.0f + 1e-8f;
    float sc_w = __uint_as_float(g_maxabs[slot_w]) / 31.0f + 1e-8f;
    int h = blockIdx.y;
    int k0 = blockIdx.x * 64;
    int tid = threadIdx.x;
    #pragma unroll
    for (int it = 0; it < 4; ++it) {
        int chunk = tid + it * 256;
        int r = chunk >> 4, c4 = (chunk & 15) * 4;
        float4 v = *(const float4*)(w + (size_t)(h * 64 + r) * D_ + k0 + c4);
        Ws[r][c4 + 0] = fminf(fmaxf(rintf(v.x / sc_w), -31.f), 31.f) * sc_w;
        Ws[r][c4 + 1] = fminf(fmaxf(rintf(v.y / sc_w), -31.f), 31.f) * sc_w;
        Ws[r][c4 + 2] = fminf(fmaxf(rintf(v.z / sc_w), -31.f), 31.f) * sc_w;
        Ws[r][c4 + 3] = fminf(fmaxf(rintf(v.w / sc_w), -31.f), 31.f) * sc_w;
    }
    #pragma unroll
    for (int it = 0; it < 4; ++it) {
        int chunk = tid + it * 256;
        int r = chunk >> 4, c4 = (chunk & 15) * 4;
        float4 v = *(const float4*)(su + (size_t)r * 64 + c4);
        Ss[r][c4 + 0] = fminf(fmaxf(rintf(v.x / sc_s), -31.f), 31.f) * sc_s;
        Ss[r][c4 + 1] = fminf(fmaxf(rintf(v.y / sc_s), -31.f), 31.f) * sc_s;
        Ss[r][c4 + 2] = fminf(fmaxf(rintf(v.z / sc_s), -31.f), 31.f) * sc_s;
        Ss[r][c4 + 3] = fminf(fmaxf(rintf(v.w / sc_s), -31.f), 31.f) * sc_s;
    }
    __syncthreads();
    int kk = (tid & 15) * 4, s0 = tid >> 4;
    float acc[4][4];
    #pragma unroll
    for (int m = 0; m < 4; ++m)
        #pragma unroll
        for (int q = 0; q < 4; ++q) acc[m][q] = 0.f;
    #pragma unroll 8
    for (int j = 0; j < 64; ++j) {
        float4 wv4 = *(const float4*)&Ws[j][kk];
        float sv0 = Ss[s0][j], sv1 = Ss[s0 + 16][j], sv2 = Ss[s0 + 32][j], sv3 = Ss[s0 + 48][j];
        acc[0][0] += sv0 * wv4.x; acc[0][1] += sv0 * wv4.y; acc[0][2] += sv0 * wv4.z; acc[0][3] += sv0 * wv4.w;
        acc[1][0] += sv1 * wv4.x; acc[1][1] += sv1 * wv4.y; acc[1][2] += sv1 * wv4.z; acc[1][3] += sv1 * wv4.w;
        acc[2][0] += sv2 * wv4.x; acc[2][1] += sv2 * wv4.y; acc[2][2] += sv2 * wv4.z; acc[2][3] += sv2 * wv4.w;
        acc[3][0] += sv3 * wv4.x; acc[3][1] += sv3 * wv4.y; acc[3][2] += sv3 * wv4.z; acc[3][3] += sv3 * wv4.w;
    }
    #pragma unroll
    for (int m = 0; m < 4; ++m) {
        size_t row = (size_t)(rowoff + h * 64 + s0 + m * 16);
        __half2 o0 = __halves2half2(__float2half(acc[m][0]), __float2half(acc[m][1]));
        __half2 o1 = __halves2half2(__float2half(acc[m][2]), __float2half(acc[m][3]));
        *(__half2*)(out + row * D_ + k0 + kk)     = o0;
        *(__half2*)(out + row * D_ + k0 + kk + 2) = o1;
    }
}

__global__ __launch_bounds__(256) void ln_half_k(const float* __restrict__ x,
                                                 const float* __restrict__ g,
                                                 const float* __restrict__ bb,
                                                 __half* __restrict__ out) {
    int row = blockIdx.x;
    const float* xr = x + (size_t)row * D_;
    int c = threadIdx.x * 4;
    float4 v = *(const float4*)(xr + c);
    float s = v.x + v.y + v.z + v.w;
    float sq = v.x * v.x + v.y * v.y + v.z * v.z + v.w * v.w;
    float2 r = block_reduce2(s, sq);
    float mu = r.x * (1.0f / D_);
    float var = r.y * (1.0f / D_) - mu * mu;
    float inv = rsqrtf(var + 1e-5f);
    float4 gg = *(const float4*)(g + c);
    float4 bv = *(const float4*)(bb + c);
    __half2 o0 = __halves2half2(__float2half((v.x - mu) * inv * gg.x + bv.x),
                                __float2half((v.y - mu) * inv * gg.y + bv.y));
    __half2 o1 = __halves2half2(__float2half((v.z - mu) * inv * gg.z + bv.z),
                                __float2half((v.w - mu) * inv * gg.w + bv.w));
    *(__half2*)(out + (size_t)row * D_ + c)     = o0;
    *(__half2*)(out + (size_t)row * D_ + c + 2) = o1;
}

__global__ __launch_bounds__(256) void rot_half_k(const __half* __restrict__ hin,
                                                  const float* __restrict__ theta,
                                                  const float* __restrict__ g,
                                                  const float* __restrict__ bb,
                                                  __half* __restrict__ out) {
    int row = blockIdx.x;
    const __half* hrow = hin + (size_t)row * HID_;
    int tid = threadIdx.x;
    float r0[6], r1[6];
    float s = 0.f, sq = 0.f;
    #pragma unroll
    for (int i = 0; i < 6; ++i) {
        int p = tid + i * 256;
        __half2 ab2 = *(const __half2*)(hrow + 2 * p);
        float ax = __half2float(__low2half(ab2));
        float ay = __half2float(__high2half(ab2));
        float sn, cs;
        sincosf(theta[p], &sn, &cs);
        r0[i] = cs * ax - sn * ay;
        r1[i] = sn * ax + cs * ay;
        s += r0[i] + r1[i];
        sq += r0[i] * r0[i] + r1[i] * r1[i];
    }
    float2 r = block_reduce2(s, sq);
    float mu = r.x * (1.0f / HID_);
    float var = r.y * (1.0f / HID_) - mu * mu;
    float inv = rsqrtf(var + 1e-5f);
    size_t base = (size_t)row * HID_;
    #pragma unroll
    for (int i = 0; i < 6; ++i) {
        int p = tid + i * 256;
        int e0 = 2 * p, e1 = 2 * p + 1;
        float y0 = (r0[i] - mu) * inv * g[e0] + bb[e0];
        float y1 = (r1[i] - mu) * inv * g[e1] + bb[e1];
        y0 = y0 / (1.0f + __expf(-y0));
        y1 = y1 / (1.0f + __expf(-y1));
        *(__half2*)(out + base + e0) = __halves2half2(__float2half(y0), __float2half(y1));
    }
}

// ---------------- host launcher ----------------
extern "C" void kernel_launch(void* const* d_in, const int* in_sizes, int n_in,
                              void* d_out, int out_size) {
    const float* x   = (const float*)d_in[0];
    const float* wq  = (const float*)d_in[1];
    const float* wk  = (const float*)d_in[2];
    const float* wv  = (const float*)d_in[3];
    const float* wo  = (const float*)d_in[4];
    const float* su  = (const float*)d_in[5];
    const float* sv  = (const float*)d_in[6];
    const float* ps  = (const float*)d_in[7];
    const float* n1g = (const float*)d_in[8];
    const float* n1b = (const float*)d_in[9];
    const float* n2g = (const float*)d_in[10];
    const float* n2b = (const float*)d_in[11];
    const float* wup = (const float*)d_in[12];
    const float* wdn = (const float*)d_in[13];
    const float* th  = (const float*)d_in[14];
    const float* mng = (const float*)d_in[15];
    const float* mnb = (const float*)d_in[16];
    float* out = (float*)d_out;

    float* hb;
    __half *ex, *eh, *eqkv, *ewo, *eup, *edn;
    cudaGetSymbolAddress((void**)&hb, g_h);
    cudaGetSymbolAddress((void**)&ex, e_x);
    cudaGetSymbolAddress((void**)&eh, e_h);
    cudaGetSymbolAddress((void**)&eqkv, e_qkv);
    cudaGetSymbolAddress((void**)&ewo, e_wo);
    cudaGetSymbolAddress((void**)&eup, e_up);
    cudaGetSymbolAddress((void**)&edn, e_dn);
    __half* hbh = (__half*)hb;

    static bool init_done = false;
    static cudaStream_t s1, s2, s3;
    static cudaEvent_t evStart, evA, evQ1, evQ2, evWV, evW3;
    if (!init_done) {
        cudaFuncSetAttribute(mm_hmma, cudaFuncAttributeMaxDynamicSharedMemorySize, MMX_SMEM);
        cudaFuncSetAttribute(flash_k, cudaFuncAttributeMaxDynamicSharedMemorySize, FL_SMEM);
        cudaStreamCreateWithFlags(&s1, cudaStreamNonBlocking);
        cudaStreamCreateWithFlags(&s2, cudaStreamNonBlocking);
        cudaStreamCreateWithFlags(&s3, cudaStreamNonBlocking);
        cudaEventCreateWithFlags(&evStart, cudaEventDisableTiming);
        cudaEventCreateWithFlags(&evA, cudaEventDisableTiming);
        cudaEventCreateWithFlags(&evQ1, cudaEventDisableTiming);
        cudaEventCreateWithFlags(&evQ2, cudaEventDisableTiming);
        cudaEventCreateWithFlags(&evWV, cudaEventDisableTiming);
        cudaEventCreateWithFlags(&evW3, cudaEventDisableTiming);
        init_done = true;
    }

    const int nDD = D_ * D_;
    const int nUP = HID_ * D_;

    cudaEventRecord(evStart, 0);
    cudaStreamWaitEvent(s1, evStart, 0);

    // ---- prep branch ----
    reset_k<<<1, 32, 0, s1>>>();
    absmax_all<<<2048, 256, 0, s1>>>(wq, wk, wv, wo, su, sv, wup, wdn);
    cudaEventRecord(evA, s1);
    cudaStreamWaitEvent(s2, evA, 0);
    cudaStreamWaitEvent(s3, evA, 0);

    fuse_stalk_q<<<dim3(D_ / 64, H_), 256, 0, s1>>>(su, wq, eqkv, 4, 0, 0);
    cudaEventRecord(evQ1, s1);
    fuse_stalk_q<<<dim3(D_ / 64, H_), 256, 0, s2>>>(sv, wk, eqkv, 5, 1, 1024);
    cudaEventRecord(evQ2, s2);
    quant_half_k<<<(nDD + 255) / 256, 256, 0, s3>>>(wv, eqkv, D_, 2, nDD, 2048);
    cudaEventRecord(evWV, s3);
    quant3_k<<<(nDD + 2 * nUP) / 256, 256, 0, s3>>>(wo, ewo, wup, eup, wdn, edn);
    cudaEventRecord(evW3, s3);

    // ---- main branch ----
    ln_half_k<<<NTOK, 256>>>(x, n1g, n1b, ex);
    cudaStreamWaitEvent(0, evQ1, 0);
    cudaStreamWaitEvent(0, evQ2, 0);
    cudaStreamWaitEvent(0, evWV, 0);
    mm_hmma<<<dim3(24, 32), 256, MMX_SMEM>>>(ex, eqkv, nullptr, nullptr, hbh, NTOK, 3 * D_, D_);
    flash_k<<<dim3(8, 64), 256, FL_SMEM>>>(hbh, ps, ex);
    cudaStreamWaitEvent(0, evW3, 0);
    mm_hmma<<<dim3(8, 32), 256, MMX_SMEM>>>(ex, ewo, x, out, nullptr, NTOK, D_, D_);

    ln_half_k<<<NTOK, 256>>>(out, n2g, n2b, ex);
    mm_hmma<<<dim3(24, 32), 256, MMX_SMEM>>>(ex, eup, nullptr, nullptr, hbh, NTOK, HID_, D_);
    rot_half_k<<<NTOK, 256>>>(hbh, th, mng, mnb, eh);
    mm_hmma<<<dim3(8, 32), 256, MMX_SMEM>>>(eh, edn, out, out, nullptr, NTOK, D_, HID_);
}